// round 1
// baseline (speedup 1.0000x reference)
#include <cuda_runtime.h>
#include <cstdint>

#define BB 4
#define TT 4096
#define DD 1024
#define HH 8
#define BUCKETS 64
#define DHH 128
#define BSZ 64
#define BHTOT (BB*HH)   // 32

// ---------------- scratch (device globals; no allocation allowed) ----------------
__device__ float g_Q  [(size_t)BHTOT * TT * DHH];           // 64 MB
__device__ float g_K  [(size_t)BHTOT * TT * DHH];           // 64 MB
__device__ float g_V  [(size_t)BHTOT * TT * DHH];           // 64 MB
__device__ float g_BKR[(size_t)BHTOT * BUCKETS * DHH];      // 1 MB
__device__ float g_R  [(size_t)BHTOT * BUCKETS * BUCKETS];  // 0.5 MB
__device__ float g_KRE[(size_t)BHTOT * BUCKETS * BSZ * DHH];// 64 MB
__device__ float g_VRE[(size_t)BHTOT * BUCKETS * BSZ * DHH];// 64 MB
__device__ float g_AO [(size_t)BB * TT * DD];               // 64 MB

// ============================================================================
// Kernel 1: qkv = x @ w_qkv^T, scattered directly into head-major Q/K/V
// C[m][n] = sum_k X[m][k] * W[n][k];  M=16384, N=3072, K=1024
// ============================================================================
__global__ __launch_bounds__(256) void gemm_qkv(const float* __restrict__ X,
                                                const float* __restrict__ W) {
    const int BM = 128, BN = 128, BK = 16;
    __shared__ float As[BK][132];
    __shared__ float Bs[BK][132];

    const int m0 = blockIdx.y * BM;
    const int n0 = blockIdx.x * BN;
    const int tid = threadIdx.x;
    const int tr = tid / 16;        // 0..15
    const int tc = tid % 16;        // 0..15

    const int lrow = tid / 4;       // 0..63
    const int lcol = (tid % 4) * 4; // 0,4,8,12

    float acc[8][8];
#pragma unroll
    for (int i = 0; i < 8; i++)
#pragma unroll
        for (int j = 0; j < 8; j++) acc[i][j] = 0.f;

    for (int k0 = 0; k0 < DD; k0 += BK) {
#pragma unroll
        for (int s = 0; s < 2; s++) {
            int r = lrow + s * 64;
            float4 a = *(const float4*)(X + (size_t)(m0 + r) * DD + k0 + lcol);
            As[lcol + 0][r] = a.x; As[lcol + 1][r] = a.y;
            As[lcol + 2][r] = a.z; As[lcol + 3][r] = a.w;
            float4 b = *(const float4*)(W + (size_t)(n0 + r) * DD + k0 + lcol);
            Bs[lcol + 0][r] = b.x; Bs[lcol + 1][r] = b.y;
            Bs[lcol + 2][r] = b.z; Bs[lcol + 3][r] = b.w;
        }
        __syncthreads();
#pragma unroll
        for (int k = 0; k < BK; k++) {
            float ra[8], rb[8];
#pragma unroll
            for (int i = 0; i < 8; i++) ra[i] = As[k][tr * 8 + i];
#pragma unroll
            for (int j = 0; j < 8; j++) rb[j] = Bs[k][tc * 8 + j];
#pragma unroll
            for (int i = 0; i < 8; i++)
#pragma unroll
                for (int j = 0; j < 8; j++) acc[i][j] += ra[i] * rb[j];
        }
        __syncthreads();
    }

    // Scatter epilogue. n0 is 128-aligned so (part, head) are block constants.
    const int part = n0 >> 10;                 // 0:q 1:k 2:v
    const int hh = (n0 & 1023) >> 7;           // head
    float* dstbase = (part == 0) ? g_Q : ((part == 1) ? g_K : g_V);
#pragma unroll
    for (int i = 0; i < 8; i++) {
        int m = m0 + tr * 8 + i;
        int b = m >> 12, t = m & 4095;
        float* rowp = dstbase + (((size_t)(b * HH + hh)) * TT + t) * DHH;
#pragma unroll
        for (int j4 = 0; j4 < 2; j4++) {
            float4 o;
            o.x = acc[i][j4 * 4 + 0]; o.y = acc[i][j4 * 4 + 1];
            o.z = acc[i][j4 * 4 + 2]; o.w = acc[i][j4 * 4 + 3];
            *(float4*)(rowp + tc * 8 + j4 * 4) = o;
        }
    }
}

// ============================================================================
// Kernel 2: bucket summaries b_k_r[bh][u][dh] = sum_i K[bh][u*64+i][dh]
// ============================================================================
__global__ __launch_bounds__(128) void bucket_sum() {
    int blk = blockIdx.x;
    int bh = blk / BUCKETS, u = blk % BUCKETS;
    int dh = threadIdx.x;
    const float* base = g_K + ((size_t)bh * TT + u * BSZ) * DHH + dh;
    float s = 0.f;
#pragma unroll 8
    for (int i = 0; i < BSZ; i++) s += base[(size_t)i * DHH];
    g_BKR[((size_t)bh * BUCKETS + u) * DHH + dh] = s;
}

// ============================================================================
// Kernel 3: R = sinkhorn(log(relu(b_k_r @ e_w)+eps) + gumbel) -> tril(exp, -1)
// One block per bh (32 blocks, 256 threads)
// ============================================================================
__global__ __launch_bounds__(256) void sinkhorn_kernel(const float* __restrict__ sort_w,
                                                       const float* __restrict__ noise_u) {
    int bh = blockIdx.x;
    int h = bh % HH;
    __shared__ float Rm[64][65];
    __shared__ float lse[64];
    int tid = threadIdx.x;

    for (int e = tid; e < 64 * 64; e += 256) {
        int u = e >> 6, v = e & 63;
        const float* bkr = g_BKR + ((size_t)bh * BUCKETS + u) * DHH;
        const float* sw  = sort_w + (size_t)h * DHH * BUCKETS + v;
        float s = 0.f;
#pragma unroll 8
        for (int d = 0; d < DHH; d++) s += bkr[d] * sw[(size_t)d * BUCKETS];
        s = fmaxf(s, 0.f);
        float r = logf(s + 1e-6f);
        float ur = noise_u[(size_t)bh * 4096 + e];
        float gum = -logf(-logf(ur + 1e-4f) + 1e-4f);
        Rm[u][v] = (r + gum) * (1.0f / 0.75f);
    }
    __syncthreads();

    for (int it = 0; it < 5; it++) {
        // rows (axis=2: over v)
        if (tid < 64) {
            float m = -1e30f;
            for (int v = 0; v < 64; v++) m = fmaxf(m, Rm[tid][v]);
            float s = 0.f;
            for (int v = 0; v < 64; v++) s += expf(Rm[tid][v] - m);
            lse[tid] = m + logf(s);
        }
        __syncthreads();
        for (int e = tid; e < 4096; e += 256) Rm[e >> 6][e & 63] -= lse[e >> 6];
        __syncthreads();
        // cols (axis=1: over u)
        if (tid < 64) {
            float m = -1e30f;
            for (int u = 0; u < 64; u++) m = fmaxf(m, Rm[u][tid]);
            float s = 0.f;
            for (int u = 0; u < 64; u++) s += expf(Rm[u][tid] - m);
            lse[tid] = m + logf(s);
        }
        __syncthreads();
        for (int e = tid; e < 4096; e += 256) Rm[e >> 6][e & 63] -= lse[e & 63];
        __syncthreads();
    }
    for (int e = tid; e < 4096; e += 256) {
        int u = e >> 6, v = e & 63;
        g_R[(size_t)bh * 4096 + e] = (u > v) ? expf(Rm[u][v]) : 0.f;
    }
}

// ============================================================================
// Kernel 4: k_re[bh][u] = sum_{v<u} R[u][v] * b_k[bh][v]   (and same for v)
// block = (u, bh, which), 256 threads, 32 elems each
// ============================================================================
__global__ __launch_bounds__(256) void permute_kv() {
    int u = blockIdx.x, bh = blockIdx.y, which = blockIdx.z;
    const float* src = which ? g_V : g_K;
    float*       dst = which ? g_VRE : g_KRE;
    __shared__ float Rrow[64];
    int tid = threadIdx.x;
    if (tid < 64) Rrow[tid] = g_R[((size_t)bh * BUCKETS + u) * BUCKETS + tid];
    __syncthreads();
    const float* sb = src + (size_t)bh * TT * DHH;
    float* db = dst + ((size_t)bh * BUCKETS + u) * BSZ * DHH;
    float acc[32];
#pragma unroll
    for (int r = 0; r < 32; r++) acc[r] = 0.f;
    for (int v = 0; v < u; v++) {          // R is strictly lower triangular
        float c = Rrow[v];
        const float* p = sb + (size_t)v * BSZ * DHH;
#pragma unroll
        for (int r = 0; r < 32; r++) acc[r] += c * p[tid + 256 * r];
    }
#pragma unroll
    for (int r = 0; r < 32; r++) db[tid + 256 * r] = acc[r];
}

// ============================================================================
// Kernel 5: bucketed attention. One block per (u, bh); 256 threads (8 warps).
// dots (64x128) = q (64x128) @ k2^T (128x128);  softmax;  out = attn @ v2.
// smem: qd[64*129] (q, then reused for attn) + kv[128*129]  = 99072 B
// ============================================================================
__global__ __launch_bounds__(256) void attention_kernel() {
    extern __shared__ float sm[];
    float* qd = sm;               // 64*129
    float* kv = sm + 64 * 129;    // 128*129
    const int u = blockIdx.x, bh = blockIdx.y;
    const int tid = threadIdx.x;
    const int warp = tid >> 5, lane = tid & 31;

    const float* Qb  = g_Q + ((size_t)bh * TT + u * BSZ) * DHH;
    const float* Kb  = g_K + ((size_t)bh * TT + u * BSZ) * DHH;
    const float* Vb  = g_V + ((size_t)bh * TT + u * BSZ) * DHH;
    const float* KRb = g_KRE + ((size_t)bh * BUCKETS + u) * BSZ * DHH;
    const float* VRb = g_VRE + ((size_t)bh * BUCKETS + u) * BSZ * DHH;

    // q rows: each warp loads its own 8 rows
#pragma unroll
    for (int ii = 0; ii < 8; ii++) {
        int i = warp * 8 + ii;
        for (int c = lane; c < 128; c += 32) qd[i * 129 + c] = Qb[(size_t)i * DHH + c];
    }
    // k2 = [k_re ; b_k]
    for (int j = warp; j < 128; j += 8) {
        const float* srow = (j < 64) ? (KRb + (size_t)j * DHH) : (Kb + (size_t)(j - 64) * DHH);
        for (int c = lane; c < 128; c += 32) kv[j * 129 + c] = srow[c];
    }
    __syncthreads();

    // dots: warp owns rows warp*8..+7; lane owns cols lane, lane+32, +64, +96
    float acc[8][4];
#pragma unroll
    for (int i = 0; i < 8; i++)
#pragma unroll
        for (int j = 0; j < 4; j++) acc[i][j] = 0.f;

    for (int dh = 0; dh < 128; dh++) {
        float rq[8], rk[4];
#pragma unroll
        for (int ii = 0; ii < 8; ii++) rq[ii] = qd[(warp * 8 + ii) * 129 + dh];
#pragma unroll
        for (int jj = 0; jj < 4; jj++) rk[jj] = kv[(lane + 32 * jj) * 129 + dh];
#pragma unroll
        for (int ii = 0; ii < 8; ii++)
#pragma unroll
            for (int jj = 0; jj < 4; jj++) acc[ii][jj] += rq[ii] * rk[jj];
    }

    // softmax per row (row fully owned by this warp)
    const float scale = 0.03125f;   // (1024)^-0.5
    float attnv[8][4];
#pragma unroll
    for (int ii = 0; ii < 8; ii++) {
        float m = -1e30f;
#pragma unroll
        for (int jj = 0; jj < 4; jj++) m = fmaxf(m, acc[ii][jj] * scale);
#pragma unroll
        for (int o = 16; o > 0; o >>= 1) m = fmaxf(m, __shfl_xor_sync(0xffffffffu, m, o));
        float s = 0.f;
#pragma unroll
        for (int jj = 0; jj < 4; jj++) {
            attnv[ii][jj] = expf(acc[ii][jj] * scale - m);
            s += attnv[ii][jj];
        }
#pragma unroll
        for (int o = 16; o > 0; o >>= 1) s += __shfl_xor_sync(0xffffffffu, s, o);
        float inv = 1.f / s;
#pragma unroll
        for (int jj = 0; jj < 4; jj++) attnv[ii][jj] *= inv;
    }

    // stash attn into qd (own rows only)
#pragma unroll
    for (int ii = 0; ii < 8; ii++)
#pragma unroll
        for (int jj = 0; jj < 4; jj++)
            qd[(warp * 8 + ii) * 129 + lane + 32 * jj] = attnv[ii][jj];
    __syncwarp();

    __syncthreads();   // all warps done reading k2
    // v2 = [v_re ; b_v]
    for (int j = warp; j < 128; j += 8) {
        const float* srow = (j < 64) ? (VRb + (size_t)j * DHH) : (Vb + (size_t)(j - 64) * DHH);
        for (int c = lane; c < 128; c += 32) kv[j * 129 + c] = srow[c];
    }
    __syncthreads();

    // out = attn @ v2
    float outr[8][4];
#pragma unroll
    for (int i = 0; i < 8; i++)
#pragma unroll
        for (int j = 0; j < 4; j++) outr[i][j] = 0.f;

    for (int j = 0; j < 128; j++) {
        float ra[8], rv[4];
#pragma unroll
        for (int ii = 0; ii < 8; ii++) ra[ii] = qd[(warp * 8 + ii) * 129 + j];
#pragma unroll
        for (int jj = 0; jj < 4; jj++) rv[jj] = kv[j * 129 + lane + 32 * jj];
#pragma unroll
        for (int ii = 0; ii < 8; ii++)
#pragma unroll
            for (int jj = 0; jj < 4; jj++) outr[ii][jj] += ra[ii] * rv[jj];
    }

    // write to (B, T, D) layout for the output GEMM
    const int b = bh >> 3, h = bh & 7;
#pragma unroll
    for (int ii = 0; ii < 8; ii++) {
        int i = warp * 8 + ii;
        int t = u * BSZ + i;
        float* row = g_AO + ((size_t)b * TT + t) * DD + h * DHH;
#pragma unroll
        for (int jj = 0; jj < 4; jj++) row[lane + 32 * jj] = outr[ii][jj];
    }
}

// ============================================================================
// Kernel 6: final = AO @ w_out^T + b_out   (M=16384, N=1024, K=1024)
// ============================================================================
__global__ __launch_bounds__(256) void gemm_out(const float* __restrict__ W,
                                                const float* __restrict__ bias,
                                                float* __restrict__ out) {
    const int BM = 128, BN = 128, BK = 16;
    __shared__ float As[BK][132];
    __shared__ float Bs[BK][132];

    const int m0 = blockIdx.y * BM;
    const int n0 = blockIdx.x * BN;
    const int tid = threadIdx.x;
    const int tr = tid / 16, tc = tid % 16;
    const int lrow = tid / 4, lcol = (tid % 4) * 4;

    float acc[8][8];
#pragma unroll
    for (int i = 0; i < 8; i++)
#pragma unroll
        for (int j = 0; j < 8; j++) acc[i][j] = 0.f;

    for (int k0 = 0; k0 < DD; k0 += BK) {
#pragma unroll
        for (int s = 0; s < 2; s++) {
            int r = lrow + s * 64;
            float4 a = *(const float4*)(g_AO + (size_t)(m0 + r) * DD + k0 + lcol);
            As[lcol + 0][r] = a.x; As[lcol + 1][r] = a.y;
            As[lcol + 2][r] = a.z; As[lcol + 3][r] = a.w;
            float4 b = *(const float4*)(W + (size_t)(n0 + r) * DD + k0 + lcol);
            Bs[lcol + 0][r] = b.x; Bs[lcol + 1][r] = b.y;
            Bs[lcol + 2][r] = b.z; Bs[lcol + 3][r] = b.w;
        }
        __syncthreads();
#pragma unroll
        for (int k = 0; k < BK; k++) {
            float ra[8], rb[8];
#pragma unroll
            for (int i = 0; i < 8; i++) ra[i] = As[k][tr * 8 + i];
#pragma unroll
            for (int j = 0; j < 8; j++) rb[j] = Bs[k][tc * 8 + j];
#pragma unroll
            for (int i = 0; i < 8; i++)
#pragma unroll
                for (int j = 0; j < 8; j++) acc[i][j] += ra[i] * rb[j];
        }
        __syncthreads();
    }

    float4 bias0 = *(const float4*)(bias + n0 + tc * 8);
    float4 bias1 = *(const float4*)(bias + n0 + tc * 8 + 4);
#pragma unroll
    for (int i = 0; i < 8; i++) {
        int m = m0 + tr * 8 + i;
        float4 o0, o1;
        o0.x = acc[i][0] + bias0.x; o0.y = acc[i][1] + bias0.y;
        o0.z = acc[i][2] + bias0.z; o0.w = acc[i][3] + bias0.w;
        o1.x = acc[i][4] + bias1.x; o1.y = acc[i][5] + bias1.y;
        o1.z = acc[i][6] + bias1.z; o1.w = acc[i][7] + bias1.w;
        *(float4*)(out + (size_t)m * DD + n0 + tc * 8)     = o0;
        *(float4*)(out + (size_t)m * DD + n0 + tc * 8 + 4) = o1;
    }
}

// ============================================================================
extern "C" void kernel_launch(void* const* d_in, const int* in_sizes, int n_in,
                              void* d_out, int out_size) {
    const float* x      = (const float*)d_in[0];
    const float* w_qkv  = (const float*)d_in[1];
    const float* sort_w = (const float*)d_in[2];
    const float* w_out  = (const float*)d_in[3];
    const float* b_out  = (const float*)d_in[4];
    const float* noise  = (const float*)d_in[5];
    float* out = (float*)d_out;

    const int ATTN_SMEM = (64 * 129 + 128 * 129) * 4;  // 99072 bytes
    cudaFuncSetAttribute(attention_kernel,
                         cudaFuncAttributeMaxDynamicSharedMemorySize, ATTN_SMEM);

    gemm_qkv<<<dim3(24, 128), 256>>>(x, w_qkv);
    bucket_sum<<<BHTOT * BUCKETS, 128>>>();
    sinkhorn_kernel<<<BHTOT, 256>>>(sort_w, noise);
    permute_kv<<<dim3(BUCKETS, BHTOT, 2), 256>>>();
    attention_kernel<<<dim3(BUCKETS, BHTOT), 256, ATTN_SMEM>>>();
    gemm_out<<<dim3(8, 128), 256>>>(w_out, b_out, out);
}

// round 5
// speedup vs baseline: 1.3079x; 1.3079x over previous
#include <cuda_runtime.h>
#include <cuda_bf16.h>
#include <cstdint>

#define BB 4
#define TT 4096
#define DD 1024
#define HH 8
#define BUCKETS 64
#define DHH 128
#define BSZ 64
#define BHTOT (BB*HH)   // 32

// ---------------- scratch (device globals; no allocation allowed) ----------------
__device__ float g_Q  [(size_t)BHTOT * TT * DHH];
__device__ float g_K  [(size_t)BHTOT * TT * DHH];
__device__ float g_V  [(size_t)BHTOT * TT * DHH];
__device__ float g_BKR[(size_t)BHTOT * BUCKETS * DHH];
__device__ float g_R  [(size_t)BHTOT * BUCKETS * BUCKETS];
__device__ float g_KRE[(size_t)BHTOT * BUCKETS * BSZ * DHH];
__device__ float g_VRE[(size_t)BHTOT * BUCKETS * BSZ * DHH];
__device__ float g_AO [(size_t)BB * TT * DD];

// =================== mma.sync helpers (baseline sm_80+ ISA) =================
__device__ __forceinline__ void mma16816(float* c, const uint32_t* a, const uint32_t* b) {
    asm volatile(
        "mma.sync.aligned.m16n8k16.row.col.f32.bf16.bf16.f32 "
        "{%0,%1,%2,%3}, {%4,%5,%6,%7}, {%8,%9}, {%0,%1,%2,%3};"
        : "+f"(c[0]), "+f"(c[1]), "+f"(c[2]), "+f"(c[3])
        : "r"(a[0]), "r"(a[1]), "r"(a[2]), "r"(a[3]), "r"(b[0]), "r"(b[1]));
}

// hi/lo bf16 split of a float4, packed as 2x uint2 (4 bf16 each, K-consecutive)
__device__ __forceinline__ void split4(float4 v, uint2& hi, uint2& lo) {
    __nv_bfloat16 h0 = __float2bfloat16(v.x), h1 = __float2bfloat16(v.y);
    __nv_bfloat16 h2 = __float2bfloat16(v.z), h3 = __float2bfloat16(v.w);
    float l0 = v.x - __bfloat162float(h0), l1 = v.y - __bfloat162float(h1);
    float l2 = v.z - __bfloat162float(h2), l3 = v.w - __bfloat162float(h3);
    __nv_bfloat16 g0 = __float2bfloat16(l0), g1 = __float2bfloat16(l1);
    __nv_bfloat16 g2 = __float2bfloat16(l2), g3 = __float2bfloat16(l3);
    hi.x = (uint32_t)__bfloat16_as_ushort(h0) | ((uint32_t)__bfloat16_as_ushort(h1) << 16);
    hi.y = (uint32_t)__bfloat16_as_ushort(h2) | ((uint32_t)__bfloat16_as_ushort(h3) << 16);
    lo.x = (uint32_t)__bfloat16_as_ushort(g0) | ((uint32_t)__bfloat16_as_ushort(g1) << 16);
    lo.y = (uint32_t)__bfloat16_as_ushort(g2) | ((uint32_t)__bfloat16_as_ushort(g3) << 16);
}

// ============================================================================
// Tensor-core GEMM via mma.sync: C[m][n] = sum_k A[m][k]*B[n][k]
// M x N x 1024, fp32 in/out, 3-pass bf16 hi/lo split.
// Block tile 128x128, BK=32, 256 threads (8 warps, each 64x32).
// SMEM pitch: 20 u32 (40 bf16) per 32-element row.
// QKV=true: A = harness input x, epilogue scatters into g_Q/K/V.
// QKV=false: A = g_AO (referenced in DEVICE code — device symbol!), writes Cout.
// ============================================================================
#define PITCH 20

template <bool QKV>
__global__ __launch_bounds__(256) void gemm_mma(const float* __restrict__ A,
                                                const float* __restrict__ Bm,
                                                const float* __restrict__ bias,
                                                float* __restrict__ Cout) {
    __shared__ uint32_t sA[2][128 * PITCH];   // [hi/lo][row*PITCH + k/2]
    __shared__ uint32_t sB[2][128 * PITCH];

    const float* Asrc = QKV ? A : (const float*)g_AO;   // device-side symbol ref

    const int tid = threadIdx.x;
    const int warp = tid >> 5, lane = tid & 31;
    const int lr = lane >> 2, lc = lane & 3;
    const int warp_m = warp >> 2;            // 0..1 -> rows warp_m*64
    const int warp_n = warp & 3;             // 0..3 -> cols warp_n*32
    const int m0 = blockIdx.y * 128;
    const int n0 = blockIdx.x * 128;

    float acc[4][4][4];
#pragma unroll
    for (int i = 0; i < 4; i++)
#pragma unroll
        for (int j = 0; j < 4; j++)
#pragma unroll
            for (int r = 0; r < 4; r++) acc[i][j][r] = 0.f;

    const int lrow = tid >> 3;       // 0..31  (row within 128, x4 groups)
    const int lc4  = tid & 7;        // float4 column 0..7

    for (int kc = 0; kc < 32; kc++) {
        // ---- load & split 128x32 fp32 of A and B into hi/lo bf16 smem ----
        const float* Ab = Asrc + (size_t)m0 * DD + kc * 32;
        const float* Bb = Bm + (size_t)n0 * DD + kc * 32;
#pragma unroll
        for (int i = 0; i < 4; i++) {
            int row = lrow + 32 * i;
            uint2 hi, lo;
            float4 va = *(const float4*)(Ab + (size_t)row * DD + lc4 * 4);
            split4(va, hi, lo);
            *(uint2*)&sA[0][row * PITCH + lc4 * 2] = hi;
            *(uint2*)&sA[1][row * PITCH + lc4 * 2] = lo;
            float4 vb = *(const float4*)(Bb + (size_t)row * DD + lc4 * 4);
            split4(vb, hi, lo);
            *(uint2*)&sB[0][row * PITCH + lc4 * 2] = hi;
            *(uint2*)&sB[1][row * PITCH + lc4 * 2] = lo;
        }
        __syncthreads();

        // ---- 2 k16 steps, 3 passes each ----
#pragma unroll
        for (int ks = 0; ks < 2; ks++) {
            uint32_t aH[4][4], aL[4][4], bH[4][2], bL[4][2];
#pragma unroll
            for (int mt = 0; mt < 4; mt++) {
                int base = (warp_m * 64 + mt * 16 + lr) * PITCH + ks * 8 + lc;
                aH[mt][0] = sA[0][base];       aH[mt][1] = sA[0][base + 8 * PITCH];
                aH[mt][2] = sA[0][base + 4];   aH[mt][3] = sA[0][base + 8 * PITCH + 4];
                aL[mt][0] = sA[1][base];       aL[mt][1] = sA[1][base + 8 * PITCH];
                aL[mt][2] = sA[1][base + 4];   aL[mt][3] = sA[1][base + 8 * PITCH + 4];
            }
#pragma unroll
            for (int nt = 0; nt < 4; nt++) {
                int base = (warp_n * 32 + nt * 8 + lr) * PITCH + ks * 8 + lc;
                bH[nt][0] = sB[0][base];  bH[nt][1] = sB[0][base + 4];
                bL[nt][0] = sB[1][base];  bL[nt][1] = sB[1][base + 4];
            }
#pragma unroll
            for (int mt = 0; mt < 4; mt++)
#pragma unroll
                for (int nt = 0; nt < 4; nt++) {
                    mma16816(acc[mt][nt], aH[mt], bH[nt]);
                    mma16816(acc[mt][nt], aH[mt], bL[nt]);
                    mma16816(acc[mt][nt], aL[mt], bH[nt]);
                }
        }
        __syncthreads();
    }

    // ---- epilogue ----
    if (QKV) {
        const int part = n0 >> 10;            // 0:q 1:k 2:v (n0 is 128-aligned)
        const int hh = (n0 & 1023) >> 7;
        float* dstbase = (part == 0) ? g_Q : ((part == 1) ? g_K : g_V);
#pragma unroll
        for (int mt = 0; mt < 4; mt++) {
#pragma unroll
            for (int half = 0; half < 2; half++) {
                int m = m0 + warp_m * 64 + mt * 16 + lr + half * 8;
                int b = m >> 12, t = m & 4095;
                float* rowp = dstbase + (((size_t)(b * HH + hh)) * TT + t) * DHH;
#pragma unroll
                for (int nt = 0; nt < 4; nt++) {
                    int ncol = warp_n * 32 + nt * 8 + lc * 2;
                    float2 o = make_float2(acc[mt][nt][half * 2], acc[mt][nt][half * 2 + 1]);
                    *(float2*)(rowp + ncol) = o;
                }
            }
        }
    } else {
#pragma unroll
        for (int mt = 0; mt < 4; mt++) {
#pragma unroll
            for (int half = 0; half < 2; half++) {
                int m = m0 + warp_m * 64 + mt * 16 + lr + half * 8;
                float* rowp = Cout + (size_t)m * DD;
#pragma unroll
                for (int nt = 0; nt < 4; nt++) {
                    int n = n0 + warp_n * 32 + nt * 8 + lc * 2;
                    float2 bv = *(const float2*)(bias + n);
                    float2 o = make_float2(acc[mt][nt][half * 2] + bv.x,
                                           acc[mt][nt][half * 2 + 1] + bv.y);
                    *(float2*)(rowp + n) = o;
                }
            }
        }
    }
}

// ============================================================================
// Kernel 2: bucket summaries
// ============================================================================
__global__ __launch_bounds__(128) void bucket_sum() {
    int blk = blockIdx.x;
    int bh = blk / BUCKETS, u = blk % BUCKETS;
    int dh = threadIdx.x;
    const float* base = g_K + ((size_t)bh * TT + u * BSZ) * DHH + dh;
    float s = 0.f;
#pragma unroll 8
    for (int i = 0; i < BSZ; i++) s += base[(size_t)i * DHH];
    g_BKR[((size_t)bh * BUCKETS + u) * DHH + dh] = s;
}

// ============================================================================
// Kernel 3: sinkhorn
// ============================================================================
__global__ __launch_bounds__(256) void sinkhorn_kernel(const float* __restrict__ sort_w,
                                                       const float* __restrict__ noise_u) {
    int bh = blockIdx.x;
    int h = bh % HH;
    __shared__ float Rm[64][65];
    __shared__ float lse[64];
    int tid = threadIdx.x;

    for (int e = tid; e < 64 * 64; e += 256) {
        int u = e >> 6, v = e & 63;
        const float* bkr = g_BKR + ((size_t)bh * BUCKETS + u) * DHH;
        const float* sw  = sort_w + (size_t)h * DHH * BUCKETS + v;
        float s = 0.f;
#pragma unroll 8
        for (int d = 0; d < DHH; d++) s += bkr[d] * sw[(size_t)d * BUCKETS];
        s = fmaxf(s, 0.f);
        float r = logf(s + 1e-6f);
        float ur = noise_u[(size_t)bh * 4096 + e];
        float gum = -logf(-logf(ur + 1e-4f) + 1e-4f);
        Rm[u][v] = (r + gum) * (1.0f / 0.75f);
    }
    __syncthreads();

    for (int it = 0; it < 5; it++) {
        if (tid < 64) {
            float m = -1e30f;
            for (int v = 0; v < 64; v++) m = fmaxf(m, Rm[tid][v]);
            float s = 0.f;
            for (int v = 0; v < 64; v++) s += expf(Rm[tid][v] - m);
            lse[tid] = m + logf(s);
        }
        __syncthreads();
        for (int e = tid; e < 4096; e += 256) Rm[e >> 6][e & 63] -= lse[e >> 6];
        __syncthreads();
        if (tid < 64) {
            float m = -1e30f;
            for (int u = 0; u < 64; u++) m = fmaxf(m, Rm[u][tid]);
            float s = 0.f;
            for (int u = 0; u < 64; u++) s += expf(Rm[u][tid] - m);
            lse[tid] = m + logf(s);
        }
        __syncthreads();
        for (int e = tid; e < 4096; e += 256) Rm[e >> 6][e & 63] -= lse[e & 63];
        __syncthreads();
    }
    for (int e = tid; e < 4096; e += 256) {
        int u = e >> 6, v = e & 63;
        g_R[(size_t)bh * 4096 + e] = (u > v) ? expf(Rm[u][v]) : 0.f;
    }
}

// ============================================================================
// Kernel 4: soft-permute via strictly-lower-triangular R (float4 loads)
// ============================================================================
__global__ __launch_bounds__(256) void permute_kv() {
    int u = blockIdx.x, bh = blockIdx.y, which = blockIdx.z;
    const float4* src = (const float4*)((which ? g_V : g_K) + (size_t)bh * TT * DHH);
    float4* dst = (float4*)((which ? g_VRE : g_KRE) + ((size_t)bh * BUCKETS + u) * BSZ * DHH);
    __shared__ float Rrow[64];
    int tid = threadIdx.x;
    if (tid < 64) Rrow[tid] = g_R[((size_t)bh * BUCKETS + u) * BUCKETS + tid];
    __syncthreads();
    float4 acc[8];
#pragma unroll
    for (int r = 0; r < 8; r++) acc[r] = make_float4(0.f, 0.f, 0.f, 0.f);
    for (int v = 0; v < u; v++) {
        float cc = Rrow[v];
        const float4* p = src + (size_t)v * 2048;   // bucket = 8192 floats
#pragma unroll
        for (int r = 0; r < 8; r++) {
            float4 t = p[tid + 256 * r];
            acc[r].x += cc * t.x; acc[r].y += cc * t.y;
            acc[r].z += cc * t.z; acc[r].w += cc * t.w;
        }
    }
#pragma unroll
    for (int r = 0; r < 8; r++) dst[tid + 256 * r] = acc[r];
}

// ============================================================================
// Kernel 5: bucketed attention
// ============================================================================
__global__ __launch_bounds__(256) void attention_kernel() {
    extern __shared__ float sm[];
    float* qd = sm;
    float* kv = sm + 64 * 129;
    const int u = blockIdx.x, bh = blockIdx.y;
    const int tid = threadIdx.x;
    const int warp = tid >> 5, lane = tid & 31;

    const float* Qb  = g_Q + ((size_t)bh * TT + u * BSZ) * DHH;
    const float* Kb  = g_K + ((size_t)bh * TT + u * BSZ) * DHH;
    const float* Vb  = g_V + ((size_t)bh * TT + u * BSZ) * DHH;
    const float* KRb = g_KRE + ((size_t)bh * BUCKETS + u) * BSZ * DHH;
    const float* VRb = g_VRE + ((size_t)bh * BUCKETS + u) * BSZ * DHH;

#pragma unroll
    for (int ii = 0; ii < 8; ii++) {
        int i = warp * 8 + ii;
        for (int c = lane; c < 128; c += 32) qd[i * 129 + c] = Qb[(size_t)i * DHH + c];
    }
    for (int j = warp; j < 128; j += 8) {
        const float* srow = (j < 64) ? (KRb + (size_t)j * DHH) : (Kb + (size_t)(j - 64) * DHH);
        for (int c = lane; c < 128; c += 32) kv[j * 129 + c] = srow[c];
    }
    __syncthreads();

    float acc[8][4];
#pragma unroll
    for (int i = 0; i < 8; i++)
#pragma unroll
        for (int j = 0; j < 4; j++) acc[i][j] = 0.f;

    for (int dh = 0; dh < 128; dh++) {
        float rq[8], rk[4];
#pragma unroll
        for (int ii = 0; ii < 8; ii++) rq[ii] = qd[(warp * 8 + ii) * 129 + dh];
#pragma unroll
        for (int jj = 0; jj < 4; jj++) rk[jj] = kv[(lane + 32 * jj) * 129 + dh];
#pragma unroll
        for (int ii = 0; ii < 8; ii++)
#pragma unroll
            for (int jj = 0; jj < 4; jj++) acc[ii][jj] += rq[ii] * rk[jj];
    }

    const float scale = 0.03125f;
    float attnv[8][4];
#pragma unroll
    for (int ii = 0; ii < 8; ii++) {
        float m = -1e30f;
#pragma unroll
        for (int jj = 0; jj < 4; jj++) m = fmaxf(m, acc[ii][jj] * scale);
#pragma unroll
        for (int o = 16; o > 0; o >>= 1) m = fmaxf(m, __shfl_xor_sync(0xffffffffu, m, o));
        float s = 0.f;
#pragma unroll
        for (int jj = 0; jj < 4; jj++) {
            attnv[ii][jj] = expf(acc[ii][jj] * scale - m);
            s += attnv[ii][jj];
        }
#pragma unroll
        for (int o = 16; o > 0; o >>= 1) s += __shfl_xor_sync(0xffffffffu, s, o);
        float inv = 1.f / s;
#pragma unroll
        for (int jj = 0; jj < 4; jj++) attnv[ii][jj] *= inv;
    }

#pragma unroll
    for (int ii = 0; ii < 8; ii++)
#pragma unroll
        for (int jj = 0; jj < 4; jj++)
            qd[(warp * 8 + ii) * 129 + lane + 32 * jj] = attnv[ii][jj];
    __syncwarp();

    __syncthreads();
    for (int j = warp; j < 128; j += 8) {
        const float* srow = (j < 64) ? (VRb + (size_t)j * DHH) : (Vb + (size_t)(j - 64) * DHH);
        for (int c = lane; c < 128; c += 32) kv[j * 129 + c] = srow[c];
    }
    __syncthreads();

    float outr[8][4];
#pragma unroll
    for (int i = 0; i < 8; i++)
#pragma unroll
        for (int j = 0; j < 4; j++) outr[i][j] = 0.f;

    for (int j = 0; j < 128; j++) {
        float ra[8], rv[4];
#pragma unroll
        for (int ii = 0; ii < 8; ii++) ra[ii] = qd[(warp * 8 + ii) * 129 + j];
#pragma unroll
        for (int jj = 0; jj < 4; jj++) rv[jj] = kv[j * 129 + lane + 32 * jj];
#pragma unroll
        for (int ii = 0; ii < 8; ii++)
#pragma unroll
            for (int jj = 0; jj < 4; jj++) outr[ii][jj] += ra[ii] * rv[jj];
    }

    const int b = bh >> 3, h = bh & 7;
#pragma unroll
    for (int ii = 0; ii < 8; ii++) {
        int i = warp * 8 + ii;
        int t = u * BSZ + i;
        float* row = g_AO + ((size_t)b * TT + t) * DD + h * DHH;
#pragma unroll
        for (int jj = 0; jj < 4; jj++) row[lane + 32 * jj] = outr[ii][jj];
    }
}

// ============================================================================
extern "C" void kernel_launch(void* const* d_in, const int* in_sizes, int n_in,
                              void* d_out, int out_size) {
    const float* x      = (const float*)d_in[0];
    const float* w_qkv  = (const float*)d_in[1];
    const float* sort_w = (const float*)d_in[2];
    const float* w_out  = (const float*)d_in[3];
    const float* b_out  = (const float*)d_in[4];
    const float* noise  = (const float*)d_in[5];
    float* out = (float*)d_out;

    const int ATTN_SMEM = (64 * 129 + 128 * 129) * 4;
    cudaFuncSetAttribute(attention_kernel,
                         cudaFuncAttributeMaxDynamicSharedMemorySize, ATTN_SMEM);

    gemm_mma<true><<<dim3(24, 128), 256>>>(x, w_qkv, nullptr, nullptr);
    bucket_sum<<<BHTOT * BUCKETS, 128>>>();
    sinkhorn_kernel<<<BHTOT, 256>>>(sort_w, noise);
    permute_kv<<<dim3(BUCKETS, BHTOT, 2), 256>>>();
    attention_kernel<<<dim3(BUCKETS, BHTOT), 256, ATTN_SMEM>>>();
    gemm_mma<false><<<dim3(8, 128), 256>>>(nullptr, w_out, b_out, out);
}

// round 6
// speedup vs baseline: 1.7956x; 1.3729x over previous
#include <cuda_runtime.h>
#include <cuda_bf16.h>
#include <cstdint>

#define BB 4
#define TT 4096
#define DD 1024
#define HH 8
#define BUCKETS 64
#define DHH 128
#define BSZ 64
#define BHTOT (BB*HH)   // 32

// ---------------- scratch (device globals; no allocation allowed) ----------------
__device__ float g_Q  [(size_t)BHTOT * TT * DHH];
__device__ float g_K  [(size_t)BHTOT * TT * DHH];
__device__ float g_V  [(size_t)BHTOT * TT * DHH];
__device__ float g_BKR[(size_t)BHTOT * BUCKETS * DHH];
__device__ float g_R  [(size_t)BHTOT * BUCKETS * BUCKETS];
__device__ float g_KRE[(size_t)BHTOT * BUCKETS * BSZ * DHH];
__device__ float g_VRE[(size_t)BHTOT * BUCKETS * BSZ * DHH];
__device__ float g_AO [(size_t)BB * TT * DD];
// bf16 hi/lo pre-split operands (A reused for x then AO; B for w_qkv then w_out)
__device__ __nv_bfloat16 g_Ahi[(size_t)16384 * 1024];
__device__ __nv_bfloat16 g_Alo[(size_t)16384 * 1024];
__device__ __nv_bfloat16 g_Bhi[(size_t)3072 * 1024];
__device__ __nv_bfloat16 g_Blo[(size_t)3072 * 1024];

// =================== helpers =================
__device__ __forceinline__ uint32_t smem_u32(const void* p) {
    uint32_t a;
    asm("{ .reg .u64 t; cvta.to.shared.u64 t, %1; cvt.u32.u64 %0, t; }" : "=r"(a) : "l"(p));
    return a;
}
__device__ __forceinline__ void cp_async16(uint32_t saddr, const void* gptr) {
    asm volatile("cp.async.cg.shared.global [%0], [%1], 16;" :: "r"(saddr), "l"(gptr));
}
#define CP_COMMIT() asm volatile("cp.async.commit_group;" ::: "memory")
#define CP_WAIT(n)  asm volatile("cp.async.wait_group %0;" :: "n"(n) : "memory")

__device__ __forceinline__ void mma16816(float* c, const uint32_t* a, const uint32_t* b) {
    asm volatile(
        "mma.sync.aligned.m16n8k16.row.col.f32.bf16.bf16.f32 "
        "{%0,%1,%2,%3}, {%4,%5,%6,%7}, {%8,%9}, {%0,%1,%2,%3};"
        : "+f"(c[0]), "+f"(c[1]), "+f"(c[2]), "+f"(c[3])
        : "r"(a[0]), "r"(a[1]), "r"(a[2]), "r"(a[3]), "r"(b[0]), "r"(b[1]));
}

__device__ __forceinline__ void split4(float4 v, uint2& hi, uint2& lo) {
    __nv_bfloat16 h0 = __float2bfloat16(v.x), h1 = __float2bfloat16(v.y);
    __nv_bfloat16 h2 = __float2bfloat16(v.z), h3 = __float2bfloat16(v.w);
    float l0 = v.x - __bfloat162float(h0), l1 = v.y - __bfloat162float(h1);
    float l2 = v.z - __bfloat162float(h2), l3 = v.w - __bfloat162float(h3);
    __nv_bfloat16 g0 = __float2bfloat16(l0), g1 = __float2bfloat16(l1);
    __nv_bfloat16 g2 = __float2bfloat16(l2), g3 = __float2bfloat16(l3);
    hi.x = (uint32_t)__bfloat16_as_ushort(h0) | ((uint32_t)__bfloat16_as_ushort(h1) << 16);
    hi.y = (uint32_t)__bfloat16_as_ushort(h2) | ((uint32_t)__bfloat16_as_ushort(h3) << 16);
    lo.x = (uint32_t)__bfloat16_as_ushort(g0) | ((uint32_t)__bfloat16_as_ushort(g1) << 16);
    lo.y = (uint32_t)__bfloat16_as_ushort(g2) | ((uint32_t)__bfloat16_as_ushort(g3) << 16);
}

// ============================================================================
// Kernel 0: pre-split fp32 -> bf16 hi/lo.  flags bit0: src=g_AO, bit1: dst=B bufs
// ============================================================================
__global__ __launch_bounds__(256) void split_kernel(const float* __restrict__ srcArg,
                                                    int nf4, int flags) {
    int i = blockIdx.x * 256 + threadIdx.x;
    if (i >= nf4) return;
    const float4* s = (const float4*)((flags & 1) ? (const float*)g_AO : srcArg);
    float4 v = s[i];
    uint2 hi, lo;
    split4(v, hi, lo);
    uint2* dh = (uint2*)((flags & 2) ? g_Bhi : g_Ahi);
    uint2* dl = (uint2*)((flags & 2) ? g_Blo : g_Alo);
    dh[i] = hi;
    dl[i] = lo;
}

// ============================================================================
// Kernel 1: tensor-core GEMM on pre-split bf16: C = A@B^T (+bias), K=1024.
// Block 128x128, BK=32, 256 threads (8 warps, 64x32 each), cp.async 2-stage.
// smem: 2 stages x 4 arrays (Ahi,Alo,Bhi,Blo) x 128 rows x PITCH(20) u32 = 80KB.
// QKV=true: epilogue scatters into g_Q/K/V.  QKV=false: writes Cout + bias.
// ============================================================================
#define PITCH 20
#define ARR_U32 (128 * PITCH)           // 2560 u32 per array
#define GSMEM_BYTES (2 * 4 * ARR_U32 * 4)  // 81920

template <bool QKV>
__global__ __launch_bounds__(256) void gemm_mma2(const float* __restrict__ bias,
                                                 float* __restrict__ Cout) {
    extern __shared__ uint32_t sm[];
    const uint32_t smbase = smem_u32(sm);

    const int tid = threadIdx.x;
    const int warp = tid >> 5, lane = tid & 31;
    const int lr = lane >> 2, lc = lane & 3;
    const int warp_m = warp >> 2;            // 0..1
    const int warp_n = warp & 3;             // 0..3
    const int m0 = blockIdx.y * 128;
    const int n0 = blockIdx.x * 128;

    const __nv_bfloat16* Ah = g_Ahi;
    const __nv_bfloat16* Al = g_Alo;
    const __nv_bfloat16* Bh = g_Bhi;
    const __nv_bfloat16* Bl = g_Blo;

    float acc[4][4][4];
#pragma unroll
    for (int i = 0; i < 4; i++)
#pragma unroll
        for (int j = 0; j < 4; j++)
#pragma unroll
            for (int r = 0; r < 4; r++) acc[i][j][r] = 0.f;

    auto prefetch = [&](int kc) {
        const int s = kc & 1;
        const size_t aoff = (size_t)m0 * DD + kc * 32;
        const size_t boff = (size_t)n0 * DD + kc * 32;
#pragma unroll
        for (int j = 0; j < 2; j++) {
            int chunk = tid + 256 * j;          // 0..511
            int row = chunk >> 2, c4 = chunk & 3;
            uint32_t sb = smbase + (uint32_t)(((s * 4) * ARR_U32 + row * PITCH + c4 * 4) * 4);
            size_t go = (size_t)row * DD + c4 * 8;
            cp_async16(sb,                   Ah + aoff + go);
            cp_async16(sb + ARR_U32 * 4,     Al + aoff + go);
            cp_async16(sb + 2 * ARR_U32 * 4, Bh + boff + go);
            cp_async16(sb + 3 * ARR_U32 * 4, Bl + boff + go);
        }
    };

    prefetch(0);
    CP_COMMIT();

    for (int kc = 0; kc < 32; kc++) {
        if (kc + 1 < 32) {
            prefetch(kc + 1);
            CP_COMMIT();
            CP_WAIT(1);
        } else {
            CP_WAIT(0);
        }
        __syncthreads();

        const uint32_t* sAh = sm + (kc & 1) * 4 * ARR_U32;
        const uint32_t* sAl = sAh + ARR_U32;
        const uint32_t* sBh = sAh + 2 * ARR_U32;
        const uint32_t* sBl = sAh + 3 * ARR_U32;

#pragma unroll
        for (int ks = 0; ks < 2; ks++) {
            uint32_t aH[4][4], aL[4][4], bH[4][2], bL[4][2];
#pragma unroll
            for (int mt = 0; mt < 4; mt++) {
                int base = (warp_m * 64 + mt * 16 + lr) * PITCH + ks * 8 + lc;
                aH[mt][0] = sAh[base];       aH[mt][1] = sAh[base + 8 * PITCH];
                aH[mt][2] = sAh[base + 4];   aH[mt][3] = sAh[base + 8 * PITCH + 4];
                aL[mt][0] = sAl[base];       aL[mt][1] = sAl[base + 8 * PITCH];
                aL[mt][2] = sAl[base + 4];   aL[mt][3] = sAl[base + 8 * PITCH + 4];
            }
#pragma unroll
            for (int nt = 0; nt < 4; nt++) {
                int base = (warp_n * 32 + nt * 8 + lr) * PITCH + ks * 8 + lc;
                bH[nt][0] = sBh[base];  bH[nt][1] = sBh[base + 4];
                bL[nt][0] = sBl[base];  bL[nt][1] = sBl[base + 4];
            }
#pragma unroll
            for (int mt = 0; mt < 4; mt++)
#pragma unroll
                for (int nt = 0; nt < 4; nt++) {
                    mma16816(acc[mt][nt], aH[mt], bH[nt]);
                    mma16816(acc[mt][nt], aH[mt], bL[nt]);
                    mma16816(acc[mt][nt], aL[mt], bH[nt]);
                }
        }
        __syncthreads();
    }

    // ---- epilogue ----
    if (QKV) {
        const int part = n0 >> 10;            // 0:q 1:k 2:v
        const int hh = (n0 & 1023) >> 7;
        float* dstbase = (part == 0) ? g_Q : ((part == 1) ? g_K : g_V);
#pragma unroll
        for (int mt = 0; mt < 4; mt++) {
#pragma unroll
            for (int half = 0; half < 2; half++) {
                int m = m0 + warp_m * 64 + mt * 16 + lr + half * 8;
                int b = m >> 12, t = m & 4095;
                float* rowp = dstbase + (((size_t)(b * HH + hh)) * TT + t) * DHH;
#pragma unroll
                for (int nt = 0; nt < 4; nt++) {
                    int ncol = warp_n * 32 + nt * 8 + lc * 2;
                    *(float2*)(rowp + ncol) =
                        make_float2(acc[mt][nt][half * 2], acc[mt][nt][half * 2 + 1]);
                }
            }
        }
    } else {
#pragma unroll
        for (int mt = 0; mt < 4; mt++) {
#pragma unroll
            for (int half = 0; half < 2; half++) {
                int m = m0 + warp_m * 64 + mt * 16 + lr + half * 8;
                float* rowp = Cout + (size_t)m * DD;
#pragma unroll
                for (int nt = 0; nt < 4; nt++) {
                    int n = n0 + warp_n * 32 + nt * 8 + lc * 2;
                    float2 bv = *(const float2*)(bias + n);
                    *(float2*)(rowp + n) =
                        make_float2(acc[mt][nt][half * 2] + bv.x,
                                    acc[mt][nt][half * 2 + 1] + bv.y);
                }
            }
        }
    }
}

// ============================================================================
// Kernel 2: bucket summaries
// ============================================================================
__global__ __launch_bounds__(128) void bucket_sum() {
    int blk = blockIdx.x;
    int bh = blk / BUCKETS, u = blk % BUCKETS;
    int dh = threadIdx.x;
    const float* base = g_K + ((size_t)bh * TT + u * BSZ) * DHH + dh;
    float s = 0.f;
#pragma unroll 8
    for (int i = 0; i < BSZ; i++) s += base[(size_t)i * DHH];
    g_BKR[((size_t)bh * BUCKETS + u) * DHH + dh] = s;
}

// ============================================================================
// Kernel 3: sinkhorn
// ============================================================================
__global__ __launch_bounds__(256) void sinkhorn_kernel(const float* __restrict__ sort_w,
                                                       const float* __restrict__ noise_u) {
    int bh = blockIdx.x;
    int h = bh % HH;
    __shared__ float Rm[64][65];
    __shared__ float lse[64];
    int tid = threadIdx.x;

    for (int e = tid; e < 64 * 64; e += 256) {
        int u = e >> 6, v = e & 63;
        const float* bkr = g_BKR + ((size_t)bh * BUCKETS + u) * DHH;
        const float* sw  = sort_w + (size_t)h * DHH * BUCKETS + v;
        float s = 0.f;
#pragma unroll 8
        for (int d = 0; d < DHH; d++) s += bkr[d] * sw[(size_t)d * BUCKETS];
        s = fmaxf(s, 0.f);
        float r = logf(s + 1e-6f);
        float ur = noise_u[(size_t)bh * 4096 + e];
        float gum = -logf(-logf(ur + 1e-4f) + 1e-4f);
        Rm[u][v] = (r + gum) * (1.0f / 0.75f);
    }
    __syncthreads();

    for (int it = 0; it < 5; it++) {
        if (tid < 64) {
            float m = -1e30f;
            for (int v = 0; v < 64; v++) m = fmaxf(m, Rm[tid][v]);
            float s = 0.f;
            for (int v = 0; v < 64; v++) s += expf(Rm[tid][v] - m);
            lse[tid] = m + logf(s);
        }
        __syncthreads();
        for (int e = tid; e < 4096; e += 256) Rm[e >> 6][e & 63] -= lse[e >> 6];
        __syncthreads();
        if (tid < 64) {
            float m = -1e30f;
            for (int u = 0; u < 64; u++) m = fmaxf(m, Rm[u][tid]);
            float s = 0.f;
            for (int u = 0; u < 64; u++) s += expf(Rm[u][tid] - m);
            lse[tid] = m + logf(s);
        }
        __syncthreads();
        for (int e = tid; e < 4096; e += 256) Rm[e >> 6][e & 63] -= lse[e & 63];
        __syncthreads();
    }
    for (int e = tid; e < 4096; e += 256) {
        int u = e >> 6, v = e & 63;
        g_R[(size_t)bh * 4096 + e] = (u > v) ? expf(Rm[u][v]) : 0.f;
    }
}

// ============================================================================
// Kernel 4 v2: soft-permute as C(64 x 8192) = R(64x64) @ B(64 x 8192) per (bh,w)
// grid (32 colblocks, 32 bh, 2 which); block 256 = 256 columns; acc[64] in regs.
// Rt[v][u] transposed in smem so LDS.128 broadcast feeds 4 FFMAs.
// Zeros in R encode the strict-lower-triangular mask.
// ============================================================================
__global__ __launch_bounds__(256) void permute_kv2() {
    __shared__ float Rt[64][64];        // [v][u], rows 256B-aligned for float4
    const int colblk = blockIdx.x, bh = blockIdx.y, which = blockIdx.z;
    const int tid = threadIdx.x;

    for (int e = tid; e < 4096; e += 256) {
        int u = e >> 6, v = e & 63;
        Rt[v][u] = g_R[(size_t)bh * 4096 + e];
    }
    __syncthreads();

    const int col = colblk * 256 + tid;                 // 0..8191 within a bucket
    const float* src = (which ? g_V : g_K) + (size_t)bh * TT * DHH + col;
    float* dst = (which ? g_VRE : g_KRE) + (size_t)bh * BUCKETS * BSZ * DHH + col;

    float acc[64];
#pragma unroll
    for (int u = 0; u < 64; u++) acc[u] = 0.f;

    for (int v = 0; v < 64; v++) {
        float b = src[(size_t)v * (BSZ * DHH)];
        const float4* rv = (const float4*)&Rt[v][0];
#pragma unroll
        for (int u4 = 0; u4 < 16; u4++) {
            float4 r = rv[u4];
            acc[u4 * 4 + 0] += r.x * b;
            acc[u4 * 4 + 1] += r.y * b;
            acc[u4 * 4 + 2] += r.z * b;
            acc[u4 * 4 + 3] += r.w * b;
        }
    }
#pragma unroll
    for (int u = 0; u < 64; u++) dst[(size_t)u * (BSZ * DHH)] = acc[u];
}

// ============================================================================
// Kernel 5: bucketed attention
// ============================================================================
__global__ __launch_bounds__(256) void attention_kernel() {
    extern __shared__ float smf[];
    float* qd = smf;
    float* kv = smf + 64 * 129;
    const int u = blockIdx.x, bh = blockIdx.y;
    const int tid = threadIdx.x;
    const int warp = tid >> 5, lane = tid & 31;

    const float* Qb  = g_Q + ((size_t)bh * TT + u * BSZ) * DHH;
    const float* Kb  = g_K + ((size_t)bh * TT + u * BSZ) * DHH;
    const float* Vb  = g_V + ((size_t)bh * TT + u * BSZ) * DHH;
    const float* KRb = g_KRE + ((size_t)bh * BUCKETS + u) * BSZ * DHH;
    const float* VRb = g_VRE + ((size_t)bh * BUCKETS + u) * BSZ * DHH;

#pragma unroll
    for (int ii = 0; ii < 8; ii++) {
        int i = warp * 8 + ii;
        for (int c = lane; c < 128; c += 32) qd[i * 129 + c] = Qb[(size_t)i * DHH + c];
    }
    for (int j = warp; j < 128; j += 8) {
        const float* srow = (j < 64) ? (KRb + (size_t)j * DHH) : (Kb + (size_t)(j - 64) * DHH);
        for (int c = lane; c < 128; c += 32) kv[j * 129 + c] = srow[c];
    }
    __syncthreads();

    float acc[8][4];
#pragma unroll
    for (int i = 0; i < 8; i++)
#pragma unroll
        for (int j = 0; j < 4; j++) acc[i][j] = 0.f;

    for (int dh = 0; dh < 128; dh++) {
        float rq[8], rk[4];
#pragma unroll
        for (int ii = 0; ii < 8; ii++) rq[ii] = qd[(warp * 8 + ii) * 129 + dh];
#pragma unroll
        for (int jj = 0; jj < 4; jj++) rk[jj] = kv[(lane + 32 * jj) * 129 + dh];
#pragma unroll
        for (int ii = 0; ii < 8; ii++)
#pragma unroll
            for (int jj = 0; jj < 4; jj++) acc[ii][jj] += rq[ii] * rk[jj];
    }

    const float scale = 0.03125f;
    float attnv[8][4];
#pragma unroll
    for (int ii = 0; ii < 8; ii++) {
        float m = -1e30f;
#pragma unroll
        for (int jj = 0; jj < 4; jj++) m = fmaxf(m, acc[ii][jj] * scale);
#pragma unroll
        for (int o = 16; o > 0; o >>= 1) m = fmaxf(m, __shfl_xor_sync(0xffffffffu, m, o));
        float s = 0.f;
#pragma unroll
        for (int jj = 0; jj < 4; jj++) {
            attnv[ii][jj] = expf(acc[ii][jj] * scale - m);
            s += attnv[ii][jj];
        }
#pragma unroll
        for (int o = 16; o > 0; o >>= 1) s += __shfl_xor_sync(0xffffffffu, s, o);
        float inv = 1.f / s;
#pragma unroll
        for (int jj = 0; jj < 4; jj++) attnv[ii][jj] *= inv;
    }

#pragma unroll
    for (int ii = 0; ii < 8; ii++)
#pragma unroll
        for (int jj = 0; jj < 4; jj++)
            qd[(warp * 8 + ii) * 129 + lane + 32 * jj] = attnv[ii][jj];
    __syncwarp();

    __syncthreads();
    for (int j = warp; j < 128; j += 8) {
        const float* srow = (j < 64) ? (VRb + (size_t)j * DHH) : (Vb + (size_t)(j - 64) * DHH);
        for (int c = lane; c < 128; c += 32) kv[j * 129 + c] = srow[c];
    }
    __syncthreads();

    float outr[8][4];
#pragma unroll
    for (int i = 0; i < 8; i++)
#pragma unroll
        for (int j = 0; j < 4; j++) outr[i][j] = 0.f;

    for (int j = 0; j < 128; j++) {
        float ra[8], rv[4];
#pragma unroll
        for (int ii = 0; ii < 8; ii++) ra[ii] = qd[(warp * 8 + ii) * 129 + j];
#pragma unroll
        for (int jj = 0; jj < 4; jj++) rv[jj] = kv[j * 129 + lane + 32 * jj];
#pragma unroll
        for (int ii = 0; ii < 8; ii++)
#pragma unroll
            for (int jj = 0; jj < 4; jj++) outr[ii][jj] += ra[ii] * rv[jj];
    }

    const int b = bh >> 3, h = bh & 7;
#pragma unroll
    for (int ii = 0; ii < 8; ii++) {
        int i = warp * 8 + ii;
        int t = u * BSZ + i;
        float* row = g_AO + ((size_t)b * TT + t) * DD + h * DHH;
#pragma unroll
        for (int jj = 0; jj < 4; jj++) row[lane + 32 * jj] = outr[ii][jj];
    }
}

// ============================================================================
extern "C" void kernel_launch(void* const* d_in, const int* in_sizes, int n_in,
                              void* d_out, int out_size) {
    const float* x      = (const float*)d_in[0];
    const float* w_qkv  = (const float*)d_in[1];
    const float* sort_w = (const float*)d_in[2];
    const float* w_out  = (const float*)d_in[3];
    const float* b_out  = (const float*)d_in[4];
    const float* noise  = (const float*)d_in[5];
    float* out = (float*)d_out;

    const int ATTN_SMEM = (64 * 129 + 128 * 129) * 4;
    cudaFuncSetAttribute(attention_kernel,
                         cudaFuncAttributeMaxDynamicSharedMemorySize, ATTN_SMEM);
    cudaFuncSetAttribute(gemm_mma2<true>,
                         cudaFuncAttributeMaxDynamicSharedMemorySize, GSMEM_BYTES);
    cudaFuncSetAttribute(gemm_mma2<false>,
                         cudaFuncAttributeMaxDynamicSharedMemorySize, GSMEM_BYTES);

    const int NF4_X = 16384 * 1024 / 4;   // 4194304
    const int NF4_WQ = 3072 * 1024 / 4;   // 786432
    const int NF4_WO = 1024 * 1024 / 4;   // 262144

    split_kernel<<<NF4_X / 256, 256>>>(x, NF4_X, 0);          // x -> A bufs
    split_kernel<<<NF4_WQ / 256, 256>>>(w_qkv, NF4_WQ, 2);    // w_qkv -> B bufs
    gemm_mma2<true><<<dim3(24, 128), 256, GSMEM_BYTES>>>(nullptr, nullptr);
    bucket_sum<<<BHTOT * BUCKETS, 128>>>();
    sinkhorn_kernel<<<BHTOT, 256>>>(sort_w, noise);
    permute_kv2<<<dim3(32, BHTOT, 2), 256>>>();
    attention_kernel<<<dim3(BUCKETS, BHTOT), 256, ATTN_SMEM>>>();
    split_kernel<<<NF4_X / 256, 256>>>(nullptr, NF4_X, 1);    // g_AO -> A bufs
    split_kernel<<<NF4_WO / 256, 256>>>(w_out, NF4_WO, 2);    // w_out -> B bufs
    gemm_mma2<false><<<dim3(8, 128), 256, GSMEM_BYTES>>>(b_out, out);
}

// round 7
// speedup vs baseline: 2.5267x; 1.4072x over previous
#include <cuda_runtime.h>
#include <cuda_fp16.h>
#include <cstdint>

#define BB 4
#define TT 4096
#define DD 1024
#define HH 8
#define BUCKETS 64
#define DHH 128
#define BSZ 64
#define BHTOT (BB*HH)   // 32

// ---------------- scratch (device globals; no allocation allowed) ----------------
__device__ float g_Q  [(size_t)BHTOT * TT * DHH];
__device__ float g_K  [(size_t)BHTOT * TT * DHH];
__device__ float g_V  [(size_t)BHTOT * TT * DHH];
__device__ float g_BKR[(size_t)BHTOT * BUCKETS * DHH];
__device__ float g_R  [(size_t)BHTOT * BUCKETS * BUCKETS];
__device__ float g_KRE[(size_t)BHTOT * BUCKETS * BSZ * DHH];
__device__ float g_VRE[(size_t)BHTOT * BUCKETS * BSZ * DHH];
__device__ float g_AO [(size_t)BB * TT * DD];
// fp16 operands (A reused for x then AO; B for w_qkv then w_out)
__device__ __half g_Ah[(size_t)16384 * 1024];
__device__ __half g_Bh[(size_t)3072 * 1024];

// =================== helpers =================
__device__ __forceinline__ uint32_t smem_u32(const void* p) {
    uint32_t a;
    asm("{ .reg .u64 t; cvta.to.shared.u64 t, %1; cvt.u32.u64 %0, t; }" : "=r"(a) : "l"(p));
    return a;
}
__device__ __forceinline__ void cp_async16(uint32_t saddr, const void* gptr) {
    asm volatile("cp.async.cg.shared.global [%0], [%1], 16;" :: "r"(saddr), "l"(gptr));
}
#define CP_COMMIT() asm volatile("cp.async.commit_group;" ::: "memory")
#define CP_WAIT(n)  asm volatile("cp.async.wait_group %0;" :: "n"(n) : "memory")

__device__ __forceinline__ void mma16816h(float* c, const uint32_t* a, const uint32_t* b) {
    asm volatile(
        "mma.sync.aligned.m16n8k16.row.col.f32.f16.f16.f32 "
        "{%0,%1,%2,%3}, {%4,%5,%6,%7}, {%8,%9}, {%0,%1,%2,%3};"
        : "+f"(c[0]), "+f"(c[1]), "+f"(c[2]), "+f"(c[3])
        : "r"(a[0]), "r"(a[1]), "r"(a[2]), "r"(a[3]), "r"(b[0]), "r"(b[1]));
}

// ============================================================================
// Kernel 0: convert fp32 -> fp16.  flags bit0: src=g_AO, bit1: dst=g_Bh
// ============================================================================
__global__ __launch_bounds__(256) void cvt_kernel(const float* __restrict__ srcArg,
                                                  int nf4, int flags) {
    int i = blockIdx.x * 256 + threadIdx.x;
    if (i >= nf4) return;
    const float4* s = (const float4*)((flags & 1) ? (const float*)g_AO : srcArg);
    float4 v = s[i];
    __half2 h0 = __floats2half2_rn(v.x, v.y);
    __half2 h1 = __floats2half2_rn(v.z, v.w);
    uint2 o;
    o.x = *(uint32_t*)&h0;
    o.y = *(uint32_t*)&h1;
    uint2* d = (uint2*)((flags & 2) ? g_Bh : g_Ah);
    d[i] = o;
}

// ============================================================================
// Kernel 1: fp16 single-pass tensor-core GEMM: C = A@B^T (+bias), K=1024.
// Block 128x128, BK=32, 256 threads (8 warps, 64x32 each), cp.async 3-stage.
// smem: 3 stages x (A,B) x 128 rows x PITCH(20) u32 = 60KB.
// ============================================================================
#define PITCH 20
#define ARR_U32 (128 * PITCH)                 // 2560 u32 per array
#define NSTAGE 3
#define GSMEM_BYTES (NSTAGE * 2 * ARR_U32 * 4)  // 61440

template <bool QKV>
__global__ __launch_bounds__(256) void gemm_h(const float* __restrict__ bias,
                                              float* __restrict__ Cout) {
    extern __shared__ uint32_t sm[];
    const uint32_t smbase = smem_u32(sm);

    const int tid = threadIdx.x;
    const int warp = tid >> 5, lane = tid & 31;
    const int lr = lane >> 2, lc = lane & 3;
    const int warp_m = warp >> 2;            // 0..1
    const int warp_n = warp & 3;             // 0..3
    const int m0 = blockIdx.y * 128;
    const int n0 = blockIdx.x * 128;

    float acc[4][4][4];
#pragma unroll
    for (int i = 0; i < 4; i++)
#pragma unroll
        for (int j = 0; j < 4; j++)
#pragma unroll
            for (int r = 0; r < 4; r++) acc[i][j][r] = 0.f;

    auto prefetch = [&](int kc) {
        const int s = kc % NSTAGE;
        const size_t aoff = (size_t)m0 * DD + kc * 32;
        const size_t boff = (size_t)n0 * DD + kc * 32;
#pragma unroll
        for (int j = 0; j < 2; j++) {
            int chunk = tid + 256 * j;          // 0..511
            int row = chunk >> 2, c4 = chunk & 3;
            uint32_t sb = smbase + (uint32_t)(((s * 2) * ARR_U32 + row * PITCH + c4 * 4) * 4);
            size_t go = (size_t)row * DD + c4 * 8;
            cp_async16(sb,               g_Ah + aoff + go);
            cp_async16(sb + ARR_U32 * 4, g_Bh + boff + go);
        }
    };

    prefetch(0); CP_COMMIT();
    prefetch(1); CP_COMMIT();

    for (int kc = 0; kc < 32; kc++) {
        if (kc + 2 < 32) {
            prefetch(kc + 2);
            CP_COMMIT();
            CP_WAIT(2);
        } else if (kc + 1 < 32) {
            CP_WAIT(1);
        } else {
            CP_WAIT(0);
        }
        __syncthreads();

        const uint32_t* sA = sm + (kc % NSTAGE) * 2 * ARR_U32;
        const uint32_t* sB = sA + ARR_U32;

#pragma unroll
        for (int ks = 0; ks < 2; ks++) {
            uint32_t aF[4][4], bF[4][2];
#pragma unroll
            for (int mt = 0; mt < 4; mt++) {
                int base = (warp_m * 64 + mt * 16 + lr) * PITCH + ks * 8 + lc;
                aF[mt][0] = sA[base];       aF[mt][1] = sA[base + 8 * PITCH];
                aF[mt][2] = sA[base + 4];   aF[mt][3] = sA[base + 8 * PITCH + 4];
            }
#pragma unroll
            for (int nt = 0; nt < 4; nt++) {
                int base = (warp_n * 32 + nt * 8 + lr) * PITCH + ks * 8 + lc;
                bF[nt][0] = sB[base];  bF[nt][1] = sB[base + 4];
            }
#pragma unroll
            for (int mt = 0; mt < 4; mt++)
#pragma unroll
                for (int nt = 0; nt < 4; nt++)
                    mma16816h(acc[mt][nt], aF[mt], bF[nt]);
        }
        __syncthreads();
    }

    // ---- epilogue ----
    if (QKV) {
        const int part = n0 >> 10;            // 0:q 1:k 2:v
        const int hh = (n0 & 1023) >> 7;
        float* dstbase = (part == 0) ? g_Q : ((part == 1) ? g_K : g_V);
#pragma unroll
        for (int mt = 0; mt < 4; mt++) {
#pragma unroll
            for (int half = 0; half < 2; half++) {
                int m = m0 + warp_m * 64 + mt * 16 + lr + half * 8;
                int b = m >> 12, t = m & 4095;
                float* rowp = dstbase + (((size_t)(b * HH + hh)) * TT + t) * DHH;
#pragma unroll
                for (int nt = 0; nt < 4; nt++) {
                    int ncol = warp_n * 32 + nt * 8 + lc * 2;
                    *(float2*)(rowp + ncol) =
                        make_float2(acc[mt][nt][half * 2], acc[mt][nt][half * 2 + 1]);
                }
            }
        }
    } else {
#pragma unroll
        for (int mt = 0; mt < 4; mt++) {
#pragma unroll
            for (int half = 0; half < 2; half++) {
                int m = m0 + warp_m * 64 + mt * 16 + lr + half * 8;
                float* rowp = Cout + (size_t)m * DD;
#pragma unroll
                for (int nt = 0; nt < 4; nt++) {
                    int n = n0 + warp_n * 32 + nt * 8 + lc * 2;
                    float2 bv = *(const float2*)(bias + n);
                    *(float2*)(rowp + n) =
                        make_float2(acc[mt][nt][half * 2] + bv.x,
                                    acc[mt][nt][half * 2 + 1] + bv.y);
                }
            }
        }
    }
}

// ============================================================================
// Kernel 2: bucket summaries
// ============================================================================
__global__ __launch_bounds__(128) void bucket_sum() {
    int blk = blockIdx.x;
    int bh = blk / BUCKETS, u = blk % BUCKETS;
    int dh = threadIdx.x;
    const float* base = g_K + ((size_t)bh * TT + u * BSZ) * DHH + dh;
    float s = 0.f;
#pragma unroll 8
    for (int i = 0; i < BSZ; i++) s += base[(size_t)i * DHH];
    g_BKR[((size_t)bh * BUCKETS + u) * DHH + dh] = s;
}

// ============================================================================
// Kernel 3: sinkhorn
// ============================================================================
__global__ __launch_bounds__(256) void sinkhorn_kernel(const float* __restrict__ sort_w,
                                                       const float* __restrict__ noise_u) {
    int bh = blockIdx.x;
    int h = bh % HH;
    __shared__ float Rm[64][65];
    __shared__ float lse[64];
    int tid = threadIdx.x;

    for (int e = tid; e < 64 * 64; e += 256) {
        int u = e >> 6, v = e & 63;
        const float* bkr = g_BKR + ((size_t)bh * BUCKETS + u) * DHH;
        const float* sw  = sort_w + (size_t)h * DHH * BUCKETS + v;
        float s = 0.f;
#pragma unroll 8
        for (int d = 0; d < DHH; d++) s += bkr[d] * sw[(size_t)d * BUCKETS];
        s = fmaxf(s, 0.f);
        float r = logf(s + 1e-6f);
        float ur = noise_u[(size_t)bh * 4096 + e];
        float gum = -logf(-logf(ur + 1e-4f) + 1e-4f);
        Rm[u][v] = (r + gum) * (1.0f / 0.75f);
    }
    __syncthreads();

    for (int it = 0; it < 5; it++) {
        if (tid < 64) {
            float m = -1e30f;
            for (int v = 0; v < 64; v++) m = fmaxf(m, Rm[tid][v]);
            float s = 0.f;
            for (int v = 0; v < 64; v++) s += expf(Rm[tid][v] - m);
            lse[tid] = m + logf(s);
        }
        __syncthreads();
        for (int e = tid; e < 4096; e += 256) Rm[e >> 6][e & 63] -= lse[e >> 6];
        __syncthreads();
        if (tid < 64) {
            float m = -1e30f;
            for (int u = 0; u < 64; u++) m = fmaxf(m, Rm[u][tid]);
            float s = 0.f;
            for (int u = 0; u < 64; u++) s += expf(Rm[u][tid] - m);
            lse[tid] = m + logf(s);
        }
        __syncthreads();
        for (int e = tid; e < 4096; e += 256) Rm[e >> 6][e & 63] -= lse[e & 63];
        __syncthreads();
    }
    for (int e = tid; e < 4096; e += 256) {
        int u = e >> 6, v = e & 63;
        g_R[(size_t)bh * 4096 + e] = (u > v) ? expf(Rm[u][v]) : 0.f;
    }
}

// ============================================================================
// Kernel 4: soft-permute as C(64 x 8192) = R(64x64) @ B(64 x 8192) per (bh,w)
// ============================================================================
__global__ __launch_bounds__(256) void permute_kv2() {
    __shared__ float Rt[64][64];        // [v][u]
    const int colblk = blockIdx.x, bh = blockIdx.y, which = blockIdx.z;
    const int tid = threadIdx.x;

    for (int e = tid; e < 4096; e += 256) {
        int u = e >> 6, v = e & 63;
        Rt[v][u] = g_R[(size_t)bh * 4096 + e];
    }
    __syncthreads();

    const int col = colblk * 256 + tid;
    const float* src = (which ? g_V : g_K) + (size_t)bh * TT * DHH + col;
    float* dst = (which ? g_VRE : g_KRE) + (size_t)bh * BUCKETS * BSZ * DHH + col;

    float acc[64];
#pragma unroll
    for (int u = 0; u < 64; u++) acc[u] = 0.f;

    for (int v = 0; v < 64; v++) {
        float b = src[(size_t)v * (BSZ * DHH)];
        const float4* rv = (const float4*)&Rt[v][0];
#pragma unroll
        for (int u4 = 0; u4 < 16; u4++) {
            float4 r = rv[u4];
            acc[u4 * 4 + 0] += r.x * b;
            acc[u4 * 4 + 1] += r.y * b;
            acc[u4 * 4 + 2] += r.z * b;
            acc[u4 * 4 + 3] += r.w * b;
        }
    }
#pragma unroll
    for (int u = 0; u < 64; u++) dst[(size_t)u * (BSZ * DHH)] = acc[u];
}

// ============================================================================
// Kernel 5: bucketed attention
// ============================================================================
__global__ __launch_bounds__(256) void attention_kernel() {
    extern __shared__ float smf[];
    float* qd = smf;
    float* kv = smf + 64 * 129;
    const int u = blockIdx.x, bh = blockIdx.y;
    const int tid = threadIdx.x;
    const int warp = tid >> 5, lane = tid & 31;

    const float* Qb  = g_Q + ((size_t)bh * TT + u * BSZ) * DHH;
    const float* Kb  = g_K + ((size_t)bh * TT + u * BSZ) * DHH;
    const float* Vb  = g_V + ((size_t)bh * TT + u * BSZ) * DHH;
    const float* KRb = g_KRE + ((size_t)bh * BUCKETS + u) * BSZ * DHH;
    const float* VRb = g_VRE + ((size_t)bh * BUCKETS + u) * BSZ * DHH;

#pragma unroll
    for (int ii = 0; ii < 8; ii++) {
        int i = warp * 8 + ii;
        for (int c = lane; c < 128; c += 32) qd[i * 129 + c] = Qb[(size_t)i * DHH + c];
    }
    for (int j = warp; j < 128; j += 8) {
        const float* srow = (j < 64) ? (KRb + (size_t)j * DHH) : (Kb + (size_t)(j - 64) * DHH);
        for (int c = lane; c < 128; c += 32) kv[j * 129 + c] = srow[c];
    }
    __syncthreads();

    float acc[8][4];
#pragma unroll
    for (int i = 0; i < 8; i++)
#pragma unroll
        for (int j = 0; j < 4; j++) acc[i][j] = 0.f;

    for (int dh = 0; dh < 128; dh++) {
        float rq[8], rk[4];
#pragma unroll
        for (int ii = 0; ii < 8; ii++) rq[ii] = qd[(warp * 8 + ii) * 129 + dh];
#pragma unroll
        for (int jj = 0; jj < 4; jj++) rk[jj] = kv[(lane + 32 * jj) * 129 + dh];
#pragma unroll
        for (int ii = 0; ii < 8; ii++)
#pragma unroll
            for (int jj = 0; jj < 4; jj++) acc[ii][jj] += rq[ii] * rk[jj];
    }

    const float scale = 0.03125f;
    float attnv[8][4];
#pragma unroll
    for (int ii = 0; ii < 8; ii++) {
        float m = -1e30f;
#pragma unroll
        for (int jj = 0; jj < 4; jj++) m = fmaxf(m, acc[ii][jj] * scale);
#pragma unroll
        for (int o = 16; o > 0; o >>= 1) m = fmaxf(m, __shfl_xor_sync(0xffffffffu, m, o));
        float s = 0.f;
#pragma unroll
        for (int jj = 0; jj < 4; jj++) {
            attnv[ii][jj] = expf(acc[ii][jj] * scale - m);
            s += attnv[ii][jj];
        }
#pragma unroll
        for (int o = 16; o > 0; o >>= 1) s += __shfl_xor_sync(0xffffffffu, s, o);
        float inv = 1.f / s;
#pragma unroll
        for (int jj = 0; jj < 4; jj++) attnv[ii][jj] *= inv;
    }

#pragma unroll
    for (int ii = 0; ii < 8; ii++)
#pragma unroll
        for (int jj = 0; jj < 4; jj++)
            qd[(warp * 8 + ii) * 129 + lane + 32 * jj] = attnv[ii][jj];
    __syncwarp();

    __syncthreads();
    for (int j = warp; j < 128; j += 8) {
        const float* srow = (j < 64) ? (VRb + (size_t)j * DHH) : (Vb + (size_t)(j - 64) * DHH);
        for (int c = lane; c < 128; c += 32) kv[j * 129 + c] = srow[c];
    }
    __syncthreads();

    float outr[8][4];
#pragma unroll
    for (int i = 0; i < 8; i++)
#pragma unroll
        for (int j = 0; j < 4; j++) outr[i][j] = 0.f;

    for (int j = 0; j < 128; j++) {
        float ra[8], rv[4];
#pragma unroll
        for (int ii = 0; ii < 8; ii++) ra[ii] = qd[(warp * 8 + ii) * 129 + j];
#pragma unroll
        for (int jj = 0; jj < 4; jj++) rv[jj] = kv[j * 129 + lane + 32 * jj];
#pragma unroll
        for (int ii = 0; ii < 8; ii++)
#pragma unroll
            for (int jj = 0; jj < 4; jj++) outr[ii][jj] += ra[ii] * rv[jj];
    }

    const int b = bh >> 3, h = bh & 7;
#pragma unroll
    for (int ii = 0; ii < 8; ii++) {
        int i = warp * 8 + ii;
        int t = u * BSZ + i;
        float* row = g_AO + ((size_t)b * TT + t) * DD + h * DHH;
#pragma unroll
        for (int jj = 0; jj < 4; jj++) row[lane + 32 * jj] = outr[ii][jj];
    }
}

// ============================================================================
extern "C" void kernel_launch(void* const* d_in, const int* in_sizes, int n_in,
                              void* d_out, int out_size) {
    const float* x      = (const float*)d_in[0];
    const float* w_qkv  = (const float*)d_in[1];
    const float* sort_w = (const float*)d_in[2];
    const float* w_out  = (const float*)d_in[3];
    const float* b_out  = (const float*)d_in[4];
    const float* noise  = (const float*)d_in[5];
    float* out = (float*)d_out;

    const int ATTN_SMEM = (64 * 129 + 128 * 129) * 4;
    cudaFuncSetAttribute(attention_kernel,
                         cudaFuncAttributeMaxDynamicSharedMemorySize, ATTN_SMEM);
    cudaFuncSetAttribute(gemm_h<true>,
                         cudaFuncAttributeMaxDynamicSharedMemorySize, GSMEM_BYTES);
    cudaFuncSetAttribute(gemm_h<false>,
                         cudaFuncAttributeMaxDynamicSharedMemorySize, GSMEM_BYTES);

    const int NF4_X = 16384 * 1024 / 4;   // 4194304
    const int NF4_WQ = 3072 * 1024 / 4;   // 786432
    const int NF4_WO = 1024 * 1024 / 4;   // 262144

    cvt_kernel<<<NF4_X / 256, 256>>>(x, NF4_X, 0);          // x -> g_Ah
    cvt_kernel<<<NF4_WQ / 256, 256>>>(w_qkv, NF4_WQ, 2);    // w_qkv -> g_Bh
    gemm_h<true><<<dim3(24, 128), 256, GSMEM_BYTES>>>(nullptr, nullptr);
    bucket_sum<<<BHTOT * BUCKETS, 128>>>();
    sinkhorn_kernel<<<BHTOT, 256>>>(sort_w, noise);
    permute_kv2<<<dim3(32, BHTOT, 2), 256>>>();
    attention_kernel<<<dim3(BUCKETS, BHTOT), 256, ATTN_SMEM>>>();
    cvt_kernel<<<NF4_X / 256, 256>>>(nullptr, NF4_X, 1);    // g_AO -> g_Ah
    cvt_kernel<<<NF4_WO / 256, 256>>>(w_out, NF4_WO, 2);    // w_out -> g_Bh
    gemm_h<false><<<dim3(8, 128), 256, GSMEM_BYTES>>>(b_out, out);
}

// round 8
// speedup vs baseline: 4.1968x; 1.6610x over previous
#include <cuda_runtime.h>
#include <cuda_fp16.h>
#include <cstdint>

#define BB 4
#define TT 4096
#define DD 1024
#define HH 8
#define BUCKETS 64
#define DHH 128
#define BSZ 64
#define BHTOT (BB*HH)   // 32

// ---------------- scratch (device globals; no allocation allowed) ----------------
__device__ __half g_Qh  [(size_t)BHTOT * TT * DHH];
__device__ __half g_Kh  [(size_t)BHTOT * TT * DHH];
__device__ __half g_Vh  [(size_t)BHTOT * TT * DHH];
__device__ __half g_KREh[(size_t)BHTOT * BUCKETS * BSZ * DHH];
__device__ __half g_VREh[(size_t)BHTOT * BUCKETS * BSZ * DHH];
__device__ float  g_BKR [(size_t)BHTOT * BUCKETS * DHH];
__device__ float  g_R   [(size_t)BHTOT * BUCKETS * BUCKETS];
// fp16 GEMM operands: A = x, later AO (written by attention); B = w_qkv, later w_out
__device__ __half g_Ah[(size_t)16384 * 1024];
__device__ __half g_Bh[(size_t)3072 * 1024];

// =================== helpers =================
__device__ __forceinline__ uint32_t smem_u32(const void* p) {
    uint32_t a;
    asm("{ .reg .u64 t; cvta.to.shared.u64 t, %1; cvt.u32.u64 %0, t; }" : "=r"(a) : "l"(p));
    return a;
}
__device__ __forceinline__ void cp_async16(uint32_t saddr, const void* gptr) {
    asm volatile("cp.async.cg.shared.global [%0], [%1], 16;" :: "r"(saddr), "l"(gptr));
}
#define CP_COMMIT() asm volatile("cp.async.commit_group;" ::: "memory")
#define CP_WAIT(n)  asm volatile("cp.async.wait_group %0;" :: "n"(n) : "memory")

__device__ __forceinline__ void mma16816h(float* c, const uint32_t* a, const uint32_t* b) {
    asm volatile(
        "mma.sync.aligned.m16n8k16.row.col.f32.f16.f16.f32 "
        "{%0,%1,%2,%3}, {%4,%5,%6,%7}, {%8,%9}, {%0,%1,%2,%3};"
        : "+f"(c[0]), "+f"(c[1]), "+f"(c[2]), "+f"(c[3])
        : "r"(a[0]), "r"(a[1]), "r"(a[2]), "r"(a[3]), "r"(b[0]), "r"(b[1]));
}

// ============================================================================
// Kernel 0: convert fp32 -> fp16.  flags bit1: dst=g_Bh else g_Ah
// ============================================================================
__global__ __launch_bounds__(256) void cvt_kernel(const float* __restrict__ src,
                                                  int nf4, int flags) {
    int i = blockIdx.x * 256 + threadIdx.x;
    if (i >= nf4) return;
    float4 v = ((const float4*)src)[i];
    __half2 h0 = __floats2half2_rn(v.x, v.y);
    __half2 h1 = __floats2half2_rn(v.z, v.w);
    uint2 o;
    o.x = *(uint32_t*)&h0;
    o.y = *(uint32_t*)&h1;
    uint2* d = (uint2*)((flags & 2) ? g_Bh : g_Ah);
    d[i] = o;
}

// ============================================================================
// Kernel 1: fp16 GEMM C = A@B^T (+bias), K=1024. 128x128 tile, 3-stage cp.async.
// QKV=true: scatter fp16 into g_Qh/g_Kh/g_Vh.  QKV=false: fp32 Cout + bias.
// ============================================================================
#define PITCH 20
#define ARR_U32 (128 * PITCH)
#define NSTAGE 3
#define GSMEM_BYTES (NSTAGE * 2 * ARR_U32 * 4)  // 61440

template <bool QKV>
__global__ __launch_bounds__(256) void gemm_h(const float* __restrict__ bias,
                                              float* __restrict__ Cout) {
    extern __shared__ uint32_t sm[];
    const uint32_t smbase = smem_u32(sm);

    const int tid = threadIdx.x;
    const int warp = tid >> 5, lane = tid & 31;
    const int lr = lane >> 2, lc = lane & 3;
    const int warp_m = warp >> 2;
    const int warp_n = warp & 3;
    const int m0 = blockIdx.y * 128;
    const int n0 = blockIdx.x * 128;

    float acc[4][4][4];
#pragma unroll
    for (int i = 0; i < 4; i++)
#pragma unroll
        for (int j = 0; j < 4; j++)
#pragma unroll
            for (int r = 0; r < 4; r++) acc[i][j][r] = 0.f;

    auto prefetch = [&](int kc) {
        const int s = kc % NSTAGE;
        const size_t aoff = (size_t)m0 * DD + kc * 32;
        const size_t boff = (size_t)n0 * DD + kc * 32;
#pragma unroll
        for (int j = 0; j < 2; j++) {
            int chunk = tid + 256 * j;
            int row = chunk >> 2, c4 = chunk & 3;
            uint32_t sb = smbase + (uint32_t)(((s * 2) * ARR_U32 + row * PITCH + c4 * 4) * 4);
            size_t go = (size_t)row * DD + c4 * 8;
            cp_async16(sb,               g_Ah + aoff + go);
            cp_async16(sb + ARR_U32 * 4, g_Bh + boff + go);
        }
    };

    prefetch(0); CP_COMMIT();
    prefetch(1); CP_COMMIT();

    for (int kc = 0; kc < 32; kc++) {
        if (kc + 2 < 32) { prefetch(kc + 2); CP_COMMIT(); CP_WAIT(2); }
        else if (kc + 1 < 32) { CP_WAIT(1); }
        else { CP_WAIT(0); }
        __syncthreads();

        const uint32_t* sA = sm + (kc % NSTAGE) * 2 * ARR_U32;
        const uint32_t* sB = sA + ARR_U32;

#pragma unroll
        for (int ks = 0; ks < 2; ks++) {
            uint32_t aF[4][4], bF[4][2];
#pragma unroll
            for (int mt = 0; mt < 4; mt++) {
                int base = (warp_m * 64 + mt * 16 + lr) * PITCH + ks * 8 + lc;
                aF[mt][0] = sA[base];       aF[mt][1] = sA[base + 8 * PITCH];
                aF[mt][2] = sA[base + 4];   aF[mt][3] = sA[base + 8 * PITCH + 4];
            }
#pragma unroll
            for (int nt = 0; nt < 4; nt++) {
                int base = (warp_n * 32 + nt * 8 + lr) * PITCH + ks * 8 + lc;
                bF[nt][0] = sB[base];  bF[nt][1] = sB[base + 4];
            }
#pragma unroll
            for (int mt = 0; mt < 4; mt++)
#pragma unroll
                for (int nt = 0; nt < 4; nt++)
                    mma16816h(acc[mt][nt], aF[mt], bF[nt]);
        }
        __syncthreads();
    }

    if (QKV) {
        const int part = n0 >> 10;
        const int hh = (n0 & 1023) >> 7;
        __half* dstbase = (part == 0) ? g_Qh : ((part == 1) ? g_Kh : g_Vh);
#pragma unroll
        for (int mt = 0; mt < 4; mt++) {
#pragma unroll
            for (int half = 0; half < 2; half++) {
                int m = m0 + warp_m * 64 + mt * 16 + lr + half * 8;
                int b = m >> 12, t = m & 4095;
                __half* rowp = dstbase + (((size_t)(b * HH + hh)) * TT + t) * DHH;
#pragma unroll
                for (int nt = 0; nt < 4; nt++) {
                    int ncol = warp_n * 32 + nt * 8 + lc * 2;
                    *(__half2*)(rowp + ncol) =
                        __floats2half2_rn(acc[mt][nt][half * 2], acc[mt][nt][half * 2 + 1]);
                }
            }
        }
    } else {
#pragma unroll
        for (int mt = 0; mt < 4; mt++) {
#pragma unroll
            for (int half = 0; half < 2; half++) {
                int m = m0 + warp_m * 64 + mt * 16 + lr + half * 8;
                float* rowp = Cout + (size_t)m * DD;
#pragma unroll
                for (int nt = 0; nt < 4; nt++) {
                    int n = n0 + warp_n * 32 + nt * 8 + lc * 2;
                    float2 bv = *(const float2*)(bias + n);
                    *(float2*)(rowp + n) =
                        make_float2(acc[mt][nt][half * 2] + bv.x,
                                    acc[mt][nt][half * 2 + 1] + bv.y);
                }
            }
        }
    }
}

// ============================================================================
// Kernel 2: bucket summaries (fp16 K, fp32 accum)
// ============================================================================
__global__ __launch_bounds__(128) void bucket_sum() {
    int blk = blockIdx.x;
    int bh = blk / BUCKETS, u = blk % BUCKETS;
    int dh = threadIdx.x;
    const __half* base = g_Kh + ((size_t)bh * TT + u * BSZ) * DHH + dh;
    float s = 0.f;
#pragma unroll 8
    for (int i = 0; i < BSZ; i++) s += __half2float(base[(size_t)i * DHH]);
    g_BKR[((size_t)bh * BUCKETS + u) * DHH + dh] = s;
}

// ============================================================================
// Kernel 3: sinkhorn (unchanged, fp32)
// ============================================================================
__global__ __launch_bounds__(256) void sinkhorn_kernel(const float* __restrict__ sort_w,
                                                       const float* __restrict__ noise_u) {
    int bh = blockIdx.x;
    int h = bh % HH;
    __shared__ float Rm[64][65];
    __shared__ float lse[64];
    int tid = threadIdx.x;

    for (int e = tid; e < 64 * 64; e += 256) {
        int u = e >> 6, v = e & 63;
        const float* bkr = g_BKR + ((size_t)bh * BUCKETS + u) * DHH;
        const float* sw  = sort_w + (size_t)h * DHH * BUCKETS + v;
        float s = 0.f;
#pragma unroll 8
        for (int d = 0; d < DHH; d++) s += bkr[d] * sw[(size_t)d * BUCKETS];
        s = fmaxf(s, 0.f);
        float r = logf(s + 1e-6f);
        float ur = noise_u[(size_t)bh * 4096 + e];
        float gum = -logf(-logf(ur + 1e-4f) + 1e-4f);
        Rm[u][v] = (r + gum) * (1.0f / 0.75f);
    }
    __syncthreads();

    for (int it = 0; it < 5; it++) {
        if (tid < 64) {
            float m = -1e30f;
            for (int v = 0; v < 64; v++) m = fmaxf(m, Rm[tid][v]);
            float s = 0.f;
            for (int v = 0; v < 64; v++) s += expf(Rm[tid][v] - m);
            lse[tid] = m + logf(s);
        }
        __syncthreads();
        for (int e = tid; e < 4096; e += 256) Rm[e >> 6][e & 63] -= lse[e >> 6];
        __syncthreads();
        if (tid < 64) {
            float m = -1e30f;
            for (int u = 0; u < 64; u++) m = fmaxf(m, Rm[u][tid]);
            float s = 0.f;
            for (int u = 0; u < 64; u++) s += expf(Rm[u][tid] - m);
            lse[tid] = m + logf(s);
        }
        __syncthreads();
        for (int e = tid; e < 4096; e += 256) Rm[e >> 6][e & 63] -= lse[e & 63];
        __syncthreads();
    }
    for (int e = tid; e < 4096; e += 256) {
        int u = e >> 6, v = e & 63;
        g_R[(size_t)bh * 4096 + e] = (u > v) ? expf(Rm[u][v]) : 0.f;
    }
}

// ============================================================================
// Kernel 4: soft-permute, fp16 src/dst, fp32 accumulate.
// C(64 x 8192) = R(64x64) @ B(64 x 8192) per (bh, which).
// ============================================================================
__global__ __launch_bounds__(256) void permute_kv2h() {
    __shared__ float Rt[64][64];        // [v][u]
    const int colblk = blockIdx.x, bh = blockIdx.y, which = blockIdx.z;
    const int tid = threadIdx.x;

    for (int e = tid; e < 4096; e += 256) {
        int u = e >> 6, v = e & 63;
        Rt[v][u] = g_R[(size_t)bh * 4096 + e];
    }
    __syncthreads();

    const int col = colblk * 256 + tid;
    const __half* src = (which ? g_Vh : g_Kh) + (size_t)bh * TT * DHH + col;
    __half* dst = (which ? g_VREh : g_KREh) + (size_t)bh * BUCKETS * BSZ * DHH + col;

    float acc[64];
#pragma unroll
    for (int u = 0; u < 64; u++) acc[u] = 0.f;

    for (int v = 0; v < 64; v++) {
        float b = __half2float(src[(size_t)v * (BSZ * DHH)]);
        const float4* rv = (const float4*)&Rt[v][0];
#pragma unroll
        for (int u4 = 0; u4 < 16; u4++) {
            float4 r = rv[u4];
            acc[u4 * 4 + 0] += r.x * b;
            acc[u4 * 4 + 1] += r.y * b;
            acc[u4 * 4 + 2] += r.z * b;
            acc[u4 * 4 + 3] += r.w * b;
        }
    }
#pragma unroll
    for (int u = 0; u < 64; u++) dst[(size_t)u * (BSZ * DHH)] = __float2half_rn(acc[u]);
}

// ============================================================================
// Kernel 5: tensor-core bucketed attention. Block = (u, bh), 256 threads.
// smem (u32 pitch AP=68 per 128-half row): Q 64r, K2 128r, V2^T 128r, P 64r,
// plus 256 floats of reduce space. dots/softmax on fragments in registers.
// Writes AO (fp16) directly into g_Ah.
// ============================================================================
#define AP 68
#define OFF_K 4352
#define OFF_V 13056
#define OFF_P 21760
#define OFF_RED 26112
#define ATTN_SMEM_B ((26112 + 256) * 4)   // 105472

__global__ __launch_bounds__(256) void attention_mma() {
    extern __shared__ uint32_t sm[];
    const int u = blockIdx.x, bh = blockIdx.y;
    const int tid = threadIdx.x;
    const int warp = tid >> 5, lane = tid & 31;
    const int lr = lane >> 2, lc = lane & 3;
    const int mt = warp & 3;      // m-tile (16 rows)
    const int nh = warp >> 2;     // n-half (64 cols)

    // ---- load Q (64x128 fp16) ----
    const __half* Qb = g_Qh + ((size_t)bh * TT + u * BSZ) * DHH;
    for (int c = tid; c < 1024; c += 256) {
        int row = c >> 4, c4 = c & 15;
        *(uint4*)(sm + row * AP + c4 * 4) = *(const uint4*)(Qb + row * 128 + c4 * 8);
    }
    // ---- load K2 = [KRE ; K] (128x128) ----
    const __half* KRb = g_KREh + ((size_t)bh * BUCKETS + u) * BSZ * DHH;
    const __half* Kb  = g_Kh + ((size_t)bh * TT + u * BSZ) * DHH;
    for (int c = tid; c < 2048; c += 256) {
        int row = c >> 4, c4 = c & 15;
        const __half* s = (row < 64) ? (KRb + row * 128 + c4 * 8)
                                     : (Kb + (row - 64) * 128 + c4 * 8);
        *(uint4*)(sm + OFF_K + row * AP + c4 * 4) = *(const uint4*)s;
    }
    // ---- load V2 transposed: sV[e][j] ----
    {
        const __half* VRb = g_VREh + ((size_t)bh * BUCKETS + u) * BSZ * DHH;
        const __half* Vb  = g_Vh + ((size_t)bh * TT + u * BSZ) * DHH;
        int j = tid >> 1, ch = (tid & 1) * 64;
        const __half* srow = (j < 64) ? (VRb + j * 128) : (Vb + (j - 64) * 128);
        __half* dsth = (__half*)(sm + OFF_V);
        for (int g = 0; g < 8; g++) {
            uint4 v = *(const uint4*)(srow + ch + g * 8);
            const __half* h = (const __half*)&v;
#pragma unroll
            for (int e = 0; e < 8; e++) dsth[(ch + g * 8 + e) * 136 + j] = h[e];
        }
    }
    __syncthreads();

    // ---- phase 1: dots = Q @ K2^T (each warp: 16 rows x 64 cols) ----
    const uint32_t* sQ = sm;
    const uint32_t* sK = sm + OFF_K;
    float c[8][4];
#pragma unroll
    for (int nt = 0; nt < 8; nt++)
#pragma unroll
        for (int r = 0; r < 4; r++) c[nt][r] = 0.f;

    for (int ks = 0; ks < 8; ks++) {
        uint32_t a[4];
        int ab = (mt * 16 + lr) * AP + ks * 8 + lc;
        a[0] = sQ[ab]; a[1] = sQ[ab + 8 * AP]; a[2] = sQ[ab + 4]; a[3] = sQ[ab + 8 * AP + 4];
#pragma unroll
        for (int nt = 0; nt < 8; nt++) {
            uint32_t b[2];
            int bb2 = (nh * 64 + nt * 8 + lr) * AP + ks * 8 + lc;
            b[0] = sK[bb2]; b[1] = sK[bb2 + 4];
            mma16816h(c[nt], a, b);
        }
    }

    // ---- softmax over n=128 (cross-warp combine via smem) ----
    const float scale = 0.03125f;
#pragma unroll
    for (int nt = 0; nt < 8; nt++)
#pragma unroll
        for (int r = 0; r < 4; r++) c[nt][r] *= scale;

    float m0 = -1e30f, m1 = -1e30f;
#pragma unroll
    for (int nt = 0; nt < 8; nt++) {
        m0 = fmaxf(m0, fmaxf(c[nt][0], c[nt][1]));
        m1 = fmaxf(m1, fmaxf(c[nt][2], c[nt][3]));
    }
    m0 = fmaxf(m0, __shfl_xor_sync(0xffffffffu, m0, 1));
    m0 = fmaxf(m0, __shfl_xor_sync(0xffffffffu, m0, 2));
    m1 = fmaxf(m1, __shfl_xor_sync(0xffffffffu, m1, 1));
    m1 = fmaxf(m1, __shfl_xor_sync(0xffffffffu, m1, 2));

    float* redM = (float*)(sm + OFF_RED);        // [nh][row] 2x64
    float* redS = redM + 128;                    // [nh][row] 2x64
    const int r0 = mt * 16 + lr, r1 = r0 + 8;
    if (lc == 0) { redM[nh * 64 + r0] = m0; redM[nh * 64 + r1] = m1; }
    __syncthreads();
    float g0 = fmaxf(redM[r0], redM[64 + r0]);
    float g1 = fmaxf(redM[r1], redM[64 + r1]);

    float s0 = 0.f, s1 = 0.f;
#pragma unroll
    for (int nt = 0; nt < 8; nt++) {
        c[nt][0] = __expf(c[nt][0] - g0);
        c[nt][1] = __expf(c[nt][1] - g0);
        c[nt][2] = __expf(c[nt][2] - g1);
        c[nt][3] = __expf(c[nt][3] - g1);
        s0 += c[nt][0] + c[nt][1];
        s1 += c[nt][2] + c[nt][3];
    }
    s0 += __shfl_xor_sync(0xffffffffu, s0, 1);
    s0 += __shfl_xor_sync(0xffffffffu, s0, 2);
    s1 += __shfl_xor_sync(0xffffffffu, s1, 1);
    s1 += __shfl_xor_sync(0xffffffffu, s1, 2);
    if (lc == 0) { redS[nh * 64 + r0] = s0; redS[nh * 64 + r1] = s1; }
    __syncthreads();
    float inv0 = 1.f / (redS[r0] + redS[64 + r0]);
    float inv1 = 1.f / (redS[r1] + redS[64 + r1]);

    // ---- pack P (fp16) into smem ----
    uint32_t* sP = sm + OFF_P;
#pragma unroll
    for (int nt = 0; nt < 8; nt++) {
        __half2 p01 = __floats2half2_rn(c[nt][0] * inv0, c[nt][1] * inv0);
        __half2 p23 = __floats2half2_rn(c[nt][2] * inv1, c[nt][3] * inv1);
        int idx = r0 * AP + nh * 32 + nt * 4 + lc;
        sP[idx] = *(uint32_t*)&p01;
        sP[idx + 8 * AP] = *(uint32_t*)&p23;
    }
    __syncthreads();

    // ---- phase 3: out = P @ V2 (B from transposed V) ----
    const uint32_t* sV = sm + OFF_V;
    float o[8][4];
#pragma unroll
    for (int nt = 0; nt < 8; nt++)
#pragma unroll
        for (int r = 0; r < 4; r++) o[nt][r] = 0.f;

    for (int ks = 0; ks < 8; ks++) {
        uint32_t a[4];
        int ab = (mt * 16 + lr) * AP + ks * 8 + lc;
        a[0] = sP[ab]; a[1] = sP[ab + 8 * AP]; a[2] = sP[ab + 4]; a[3] = sP[ab + 8 * AP + 4];
#pragma unroll
        for (int nt = 0; nt < 8; nt++) {
            uint32_t b[2];
            int bb2 = (nh * 64 + nt * 8 + lr) * AP + ks * 8 + lc;
            b[0] = sV[bb2]; b[1] = sV[bb2 + 4];
            mma16816h(o[nt], a, b);
        }
    }

    // ---- epilogue: fp16 AO directly into g_Ah ----
    const int bb = bh >> 3, hh = bh & 7;
    const size_t row0 = (size_t)bb * TT + u * BSZ + mt * 16 + lr;
#pragma unroll
    for (int nt = 0; nt < 8; nt++) {
        int col = hh * 128 + nh * 64 + nt * 8 + lc * 2;
        *(__half2*)(g_Ah + row0 * DD + col)       = __floats2half2_rn(o[nt][0], o[nt][1]);
        *(__half2*)(g_Ah + (row0 + 8) * DD + col) = __floats2half2_rn(o[nt][2], o[nt][3]);
    }
}

// ============================================================================
extern "C" void kernel_launch(void* const* d_in, const int* in_sizes, int n_in,
                              void* d_out, int out_size) {
    const float* x      = (const float*)d_in[0];
    const float* w_qkv  = (const float*)d_in[1];
    const float* sort_w = (const float*)d_in[2];
    const float* w_out  = (const float*)d_in[3];
    const float* b_out  = (const float*)d_in[4];
    const float* noise  = (const float*)d_in[5];
    float* out = (float*)d_out;

    cudaFuncSetAttribute(attention_mma,
                         cudaFuncAttributeMaxDynamicSharedMemorySize, ATTN_SMEM_B);
    cudaFuncSetAttribute(gemm_h<true>,
                         cudaFuncAttributeMaxDynamicSharedMemorySize, GSMEM_BYTES);
    cudaFuncSetAttribute(gemm_h<false>,
                         cudaFuncAttributeMaxDynamicSharedMemorySize, GSMEM_BYTES);

    const int NF4_X  = 16384 * 1024 / 4;
    const int NF4_WQ = 3072 * 1024 / 4;
    const int NF4_WO = 1024 * 1024 / 4;

    cvt_kernel<<<NF4_X / 256, 256>>>(x, NF4_X, 0);          // x -> g_Ah
    cvt_kernel<<<NF4_WQ / 256, 256>>>(w_qkv, NF4_WQ, 2);    // w_qkv -> g_Bh
    gemm_h<true><<<dim3(24, 128), 256, GSMEM_BYTES>>>(nullptr, nullptr);
    bucket_sum<<<BHTOT * BUCKETS, 128>>>();
    sinkhorn_kernel<<<BHTOT, 256>>>(sort_w, noise);
    permute_kv2h<<<dim3(32, BHTOT, 2), 256>>>();
    attention_mma<<<dim3(BUCKETS, BHTOT), 256, ATTN_SMEM_B>>>();  // AO -> g_Ah (fp16)
    cvt_kernel<<<NF4_WO / 256, 256>>>(w_out, NF4_WO, 2);    // w_out -> g_Bh
    gemm_h<false><<<dim3(8, 128), 256, GSMEM_BYTES>>>(b_out, out);
}

// round 9
// speedup vs baseline: 4.4840x; 1.0684x over previous
#include <cuda_runtime.h>
#include <cuda_fp16.h>
#include <cstdint>

#define BB 4
#define TT 4096
#define DD 1024
#define HH 8
#define BUCKETS 64
#define DHH 128
#define BSZ 64
#define BHTOT (BB*HH)   // 32

// ---------------- scratch (device globals; no allocation allowed) ----------------
__device__ __half g_Qh  [(size_t)BHTOT * TT * DHH];
__device__ __half g_Kh  [(size_t)BHTOT * TT * DHH];
__device__ __half g_Vh  [(size_t)BHTOT * TT * DHH];
__device__ __half g_KREh[(size_t)BHTOT * BUCKETS * BSZ * DHH];
__device__ __half g_VREh[(size_t)BHTOT * BUCKETS * BSZ * DHH];
__device__ float  g_BKR [(size_t)BHTOT * BUCKETS * DHH];
__device__ float  g_R   [(size_t)BHTOT * BUCKETS * BUCKETS];
__device__ __half g_Ah[(size_t)16384 * 1024];
__device__ __half g_Bh[(size_t)3072 * 1024];

// =================== helpers =================
__device__ __forceinline__ uint32_t smem_u32(const void* p) {
    uint32_t a;
    asm("{ .reg .u64 t; cvta.to.shared.u64 t, %1; cvt.u32.u64 %0, t; }" : "=r"(a) : "l"(p));
    return a;
}
__device__ __forceinline__ void cp_async16(uint32_t saddr, const void* gptr) {
    asm volatile("cp.async.cg.shared.global [%0], [%1], 16;" :: "r"(saddr), "l"(gptr));
}
#define CP_COMMIT() asm volatile("cp.async.commit_group;" ::: "memory")
#define CP_WAIT(n)  asm volatile("cp.async.wait_group %0;" :: "n"(n) : "memory")

__device__ __forceinline__ void mma16816h(float* c, const uint32_t* a, const uint32_t* b) {
    asm volatile(
        "mma.sync.aligned.m16n8k16.row.col.f32.f16.f16.f32 "
        "{%0,%1,%2,%3}, {%4,%5,%6,%7}, {%8,%9}, {%0,%1,%2,%3};"
        : "+f"(c[0]), "+f"(c[1]), "+f"(c[2]), "+f"(c[3])
        : "r"(a[0]), "r"(a[1]), "r"(a[2]), "r"(a[3]), "r"(b[0]), "r"(b[1]));
}
__device__ __forceinline__ void ldsm_x4(uint32_t* r, uint32_t saddr) {
    asm volatile("ldmatrix.sync.aligned.m8n8.x4.shared.b16 {%0,%1,%2,%3}, [%4];"
        : "=r"(r[0]), "=r"(r[1]), "=r"(r[2]), "=r"(r[3]) : "r"(saddr));
}
__device__ __forceinline__ void ldsm_x2(uint32_t* r, uint32_t saddr) {
    asm volatile("ldmatrix.sync.aligned.m8n8.x2.shared.b16 {%0,%1}, [%2];"
        : "=r"(r[0]), "=r"(r[1]) : "r"(saddr));
}
__device__ __forceinline__ void ldsm_x2_t(uint32_t* r, uint32_t saddr) {
    asm volatile("ldmatrix.sync.aligned.m8n8.x2.trans.shared.b16 {%0,%1}, [%2];"
        : "=r"(r[0]), "=r"(r[1]) : "r"(saddr));
}

// ============================================================================
// Kernel 0: convert fp32 -> fp16.  flags bit1: dst=g_Bh else g_Ah
// ============================================================================
__global__ __launch_bounds__(256) void cvt_kernel(const float* __restrict__ src,
                                                  int nf4, int flags) {
    int i = blockIdx.x * 256 + threadIdx.x;
    if (i >= nf4) return;
    float4 v = ((const float4*)src)[i];
    __half2 h0 = __floats2half2_rn(v.x, v.y);
    __half2 h1 = __floats2half2_rn(v.z, v.w);
    uint2 o;
    o.x = *(uint32_t*)&h0;
    o.y = *(uint32_t*)&h1;
    uint2* d = (uint2*)((flags & 2) ? g_Bh : g_Ah);
    d[i] = o;
}

// ============================================================================
// Kernel 1: fp16 GEMM C = A@B^T (+bias), K=1024, ldmatrix operand loads.
// ============================================================================
#define PITCH 20
#define ARR_U32 (128 * PITCH)
#define NSTAGE 3
#define GSMEM_BYTES (NSTAGE * 2 * ARR_U32 * 4)  // 61440

template <bool QKV>
__global__ __launch_bounds__(256) void gemm_h(const float* __restrict__ bias,
                                              float* __restrict__ Cout) {
    extern __shared__ uint32_t sm[];
    const uint32_t smbase = smem_u32(sm);

    const int tid = threadIdx.x;
    const int warp = tid >> 5, lane = tid & 31;
    const int lr = lane >> 2, lc = lane & 3;
    const int warp_m = warp >> 2;
    const int warp_n = warp & 3;
    const int m0 = blockIdx.y * 128;
    const int n0 = blockIdx.x * 128;

    // per-lane ldmatrix row offsets (u32 units)
    const uint32_t a_loff = (uint32_t)(((lane & 7) + ((lane >> 3) & 1) * 8) * PITCH
                                       + ((lane >> 4) & 1) * 4);
    const uint32_t b_loff = (uint32_t)((lane & 7) * PITCH + ((lane >> 3) & 1) * 4);

    float acc[4][4][4];
#pragma unroll
    for (int i = 0; i < 4; i++)
#pragma unroll
        for (int j = 0; j < 4; j++)
#pragma unroll
            for (int r = 0; r < 4; r++) acc[i][j][r] = 0.f;

    auto prefetch = [&](int kc) {
        const int s = kc % NSTAGE;
        const size_t aoff = (size_t)m0 * DD + kc * 32;
        const size_t boff = (size_t)n0 * DD + kc * 32;
#pragma unroll
        for (int j = 0; j < 2; j++) {
            int chunk = tid + 256 * j;
            int row = chunk >> 2, c4 = chunk & 3;
            uint32_t sb = smbase + (uint32_t)(((s * 2) * ARR_U32 + row * PITCH + c4 * 4) * 4);
            size_t go = (size_t)row * DD + c4 * 8;
            cp_async16(sb,               g_Ah + aoff + go);
            cp_async16(sb + ARR_U32 * 4, g_Bh + boff + go);
        }
    };

    prefetch(0); CP_COMMIT();
    prefetch(1); CP_COMMIT();

    for (int kc = 0; kc < 32; kc++) {
        if (kc + 2 < 32) { prefetch(kc + 2); CP_COMMIT(); CP_WAIT(2); }
        else if (kc + 1 < 32) { CP_WAIT(1); }
        else { CP_WAIT(0); }
        __syncthreads();

        const uint32_t stA = smbase + (uint32_t)((kc % NSTAGE) * 2 * ARR_U32 * 4);
        const uint32_t stB = stA + (uint32_t)(ARR_U32 * 4);

#pragma unroll
        for (int ks = 0; ks < 2; ks++) {
            uint32_t aF[4][4], bF[4][2];
#pragma unroll
            for (int mt = 0; mt < 4; mt++)
                ldsm_x4(aF[mt], stA + (uint32_t)(((warp_m * 64 + mt * 16) * PITCH + ks * 8) * 4)
                                     + a_loff * 4);
#pragma unroll
            for (int nt = 0; nt < 4; nt++)
                ldsm_x2(bF[nt], stB + (uint32_t)(((warp_n * 32 + nt * 8) * PITCH + ks * 8) * 4)
                                     + b_loff * 4);
#pragma unroll
            for (int mt = 0; mt < 4; mt++)
#pragma unroll
                for (int nt = 0; nt < 4; nt++)
                    mma16816h(acc[mt][nt], aF[mt], bF[nt]);
        }
        __syncthreads();
    }

    if (QKV) {
        const int part = n0 >> 10;
        const int hh = (n0 & 1023) >> 7;
        __half* dstbase = (part == 0) ? g_Qh : ((part == 1) ? g_Kh : g_Vh);
#pragma unroll
        for (int mt = 0; mt < 4; mt++) {
#pragma unroll
            for (int half = 0; half < 2; half++) {
                int m = m0 + warp_m * 64 + mt * 16 + lr + half * 8;
                int b = m >> 12, t = m & 4095;
                __half* rowp = dstbase + (((size_t)(b * HH + hh)) * TT + t) * DHH;
#pragma unroll
                for (int nt = 0; nt < 4; nt++) {
                    int ncol = warp_n * 32 + nt * 8 + lc * 2;
                    *(__half2*)(rowp + ncol) =
                        __floats2half2_rn(acc[mt][nt][half * 2], acc[mt][nt][half * 2 + 1]);
                }
            }
        }
    } else {
#pragma unroll
        for (int mt = 0; mt < 4; mt++) {
#pragma unroll
            for (int half = 0; half < 2; half++) {
                int m = m0 + warp_m * 64 + mt * 16 + lr + half * 8;
                float* rowp = Cout + (size_t)m * DD;
#pragma unroll
                for (int nt = 0; nt < 4; nt++) {
                    int n = n0 + warp_n * 32 + nt * 8 + lc * 2;
                    float2 bv = *(const float2*)(bias + n);
                    *(float2*)(rowp + n) =
                        make_float2(acc[mt][nt][half * 2] + bv.x,
                                    acc[mt][nt][half * 2 + 1] + bv.y);
                }
            }
        }
    }
}

// ============================================================================
// Kernel 2: bucket summaries
// ============================================================================
__global__ __launch_bounds__(128) void bucket_sum() {
    int blk = blockIdx.x;
    int bh = blk / BUCKETS, u = blk % BUCKETS;
    int dh = threadIdx.x;
    const __half* base = g_Kh + ((size_t)bh * TT + u * BSZ) * DHH + dh;
    float s = 0.f;
#pragma unroll 8
    for (int i = 0; i < BSZ; i++) s += __half2float(base[(size_t)i * DHH]);
    g_BKR[((size_t)bh * BUCKETS + u) * DHH + dh] = s;
}

// ============================================================================
// Kernel 3: sinkhorn (fp32)
// ============================================================================
__global__ __launch_bounds__(256) void sinkhorn_kernel(const float* __restrict__ sort_w,
                                                       const float* __restrict__ noise_u) {
    int bh = blockIdx.x;
    int h = bh % HH;
    __shared__ float Rm[64][65];
    __shared__ float lse[64];
    int tid = threadIdx.x;

    for (int e = tid; e < 64 * 64; e += 256) {
        int u = e >> 6, v = e & 63;
        const float* bkr = g_BKR + ((size_t)bh * BUCKETS + u) * DHH;
        const float* sw  = sort_w + (size_t)h * DHH * BUCKETS + v;
        float s = 0.f;
#pragma unroll 8
        for (int d = 0; d < DHH; d++) s += bkr[d] * sw[(size_t)d * BUCKETS];
        s = fmaxf(s, 0.f);
        float r = logf(s + 1e-6f);
        float ur = noise_u[(size_t)bh * 4096 + e];
        float gum = -logf(-logf(ur + 1e-4f) + 1e-4f);
        Rm[u][v] = (r + gum) * (1.0f / 0.75f);
    }
    __syncthreads();

    for (int it = 0; it < 5; it++) {
        if (tid < 64) {
            float m = -1e30f;
            for (int v = 0; v < 64; v++) m = fmaxf(m, Rm[tid][v]);
            float s = 0.f;
            for (int v = 0; v < 64; v++) s += expf(Rm[tid][v] - m);
            lse[tid] = m + logf(s);
        }
        __syncthreads();
        for (int e = tid; e < 4096; e += 256) Rm[e >> 6][e & 63] -= lse[e >> 6];
        __syncthreads();
        if (tid < 64) {
            float m = -1e30f;
            for (int u = 0; u < 64; u++) m = fmaxf(m, Rm[u][tid]);
            float s = 0.f;
            for (int u = 0; u < 64; u++) s += expf(Rm[u][tid] - m);
            lse[tid] = m + logf(s);
        }
        __syncthreads();
        for (int e = tid; e < 4096; e += 256) Rm[e >> 6][e & 63] -= lse[e & 63];
        __syncthreads();
    }
    for (int e = tid; e < 4096; e += 256) {
        int u = e >> 6, v = e & 63;
        g_R[(size_t)bh * 4096 + e] = (u > v) ? expf(Rm[u][v]) : 0.f;
    }
}

// ============================================================================
// Kernel 4: soft-permute, tril-pruned: skip u4 groups that are all-zero in R.
// ============================================================================
__global__ __launch_bounds__(256) void permute_kv2h() {
    __shared__ float Rt[64][64];        // [v][u]
    const int colblk = blockIdx.x, bh = blockIdx.y, which = blockIdx.z;
    const int tid = threadIdx.x;

    for (int e = tid; e < 4096; e += 256) {
        int u = e >> 6, v = e & 63;
        Rt[v][u] = g_R[(size_t)bh * 4096 + e];
    }
    __syncthreads();

    const int col = colblk * 256 + tid;
    const __half* src = (which ? g_Vh : g_Kh) + (size_t)bh * TT * DHH + col;
    __half* dst = (which ? g_VREh : g_KREh) + (size_t)bh * BUCKETS * BSZ * DHH + col;

    float acc[64];
#pragma unroll
    for (int u = 0; u < 64; u++) acc[u] = 0.f;

#pragma unroll
    for (int v = 0; v < 63; v++) {      // v=63 contributes to no u (strict tril)
        float b = __half2float(src[(size_t)v * (BSZ * DHH)]);
#pragma unroll
        for (int u4 = 0; u4 < 16; u4++) {
            if (u4 * 4 + 3 > v) {       // compile-time prune: R[u][v]=0 for u<=v
                float4 r = *(const float4*)&Rt[v][u4 * 4];
                acc[u4 * 4 + 0] += r.x * b;
                acc[u4 * 4 + 1] += r.y * b;
                acc[u4 * 4 + 2] += r.z * b;
                acc[u4 * 4 + 3] += r.w * b;
            }
        }
    }
#pragma unroll
    for (int u = 0; u < 64; u++) dst[(size_t)u * (BSZ * DHH)] = __float2half_rn(acc[u]);
}

// ============================================================================
// Kernel 5: tensor-core attention, ldmatrix operands, trans-ldmatrix for V2.
// smem u32 (AP=68): Q 64r @0, K2 128r @OFF_K, V2 128r @OFF_V (row-major now),
// P 64r @OFF_P, reduce @OFF_RED.
// ============================================================================
#define AP 68
#define OFF_K 4352
#define OFF_V 13056
#define OFF_P 21760
#define OFF_RED 26112
#define ATTN_SMEM_B ((26112 + 256) * 4)   // 105472

__global__ __launch_bounds__(256) void attention_mma() {
    extern __shared__ uint32_t sm[];
    const uint32_t smbase = smem_u32(sm);
    const int u = blockIdx.x, bh = blockIdx.y;
    const int tid = threadIdx.x;
    const int warp = tid >> 5, lane = tid & 31;
    const int lr = lane >> 2, lc = lane & 3;
    const int mt = warp & 3;      // m-tile (16 rows)
    const int nh = warp >> 2;     // n-half (64 cols)

    // per-lane ldmatrix offsets (u32)
    const uint32_t a_loff = (uint32_t)(((lane & 7) + ((lane >> 3) & 1) * 8) * AP
                                       + ((lane >> 4) & 1) * 4);
    const uint32_t b_loff = (uint32_t)((lane & 7) * AP + ((lane >> 3) & 1) * 4);
    const uint32_t t_loff = (uint32_t)(((lane & 7) + ((lane >> 3) & 1) * 8) * AP);

    // ---- load Q (64x128) ----
    const __half* Qb = g_Qh + ((size_t)bh * TT + u * BSZ) * DHH;
    for (int c = tid; c < 1024; c += 256) {
        int row = c >> 4, c4 = c & 15;
        *(uint4*)(sm + row * AP + c4 * 4) = *(const uint4*)(Qb + row * 128 + c4 * 8);
    }
    // ---- load K2 = [KRE ; K] (128x128) ----
    const __half* KRb = g_KREh + ((size_t)bh * BUCKETS + u) * BSZ * DHH;
    const __half* Kb  = g_Kh + ((size_t)bh * TT + u * BSZ) * DHH;
    for (int c = tid; c < 2048; c += 256) {
        int row = c >> 4, c4 = c & 15;
        const __half* s = (row < 64) ? (KRb + row * 128 + c4 * 8)
                                     : (Kb + (row - 64) * 128 + c4 * 8);
        *(uint4*)(sm + OFF_K + row * AP + c4 * 4) = *(const uint4*)s;
    }
    // ---- load V2 = [VRE ; V] row-major (128x128) ----
    const __half* VRb = g_VREh + ((size_t)bh * BUCKETS + u) * BSZ * DHH;
    const __half* Vb  = g_Vh + ((size_t)bh * TT + u * BSZ) * DHH;
    for (int c = tid; c < 2048; c += 256) {
        int row = c >> 4, c4 = c & 15;
        const __half* s = (row < 64) ? (VRb + row * 128 + c4 * 8)
                                     : (Vb + (row - 64) * 128 + c4 * 8);
        *(uint4*)(sm + OFF_V + row * AP + c4 * 4) = *(const uint4*)s;
    }
    __syncthreads();

    // ---- phase 1: dots = Q @ K2^T ----
    float c[8][4];
#pragma unroll
    for (int nt = 0; nt < 8; nt++)
#pragma unroll
        for (int r = 0; r < 4; r++) c[nt][r] = 0.f;

#pragma unroll
    for (int ks = 0; ks < 8; ks++) {
        uint32_t a[4];
        ldsm_x4(a, smbase + (uint32_t)(((mt * 16) * AP + ks * 8) * 4) + a_loff * 4);
#pragma unroll
        for (int nt = 0; nt < 8; nt++) {
            uint32_t b[2];
            ldsm_x2(b, smbase + (uint32_t)((OFF_K + (nh * 64 + nt * 8) * AP + ks * 8) * 4)
                              + b_loff * 4);
            mma16816h(c[nt], a, b);
        }
    }

    // ---- softmax over n=128 ----
    const float scale = 0.03125f;
#pragma unroll
    for (int nt = 0; nt < 8; nt++)
#pragma unroll
        for (int r = 0; r < 4; r++) c[nt][r] *= scale;

    float m0 = -1e30f, m1 = -1e30f;
#pragma unroll
    for (int nt = 0; nt < 8; nt++) {
        m0 = fmaxf(m0, fmaxf(c[nt][0], c[nt][1]));
        m1 = fmaxf(m1, fmaxf(c[nt][2], c[nt][3]));
    }
    m0 = fmaxf(m0, __shfl_xor_sync(0xffffffffu, m0, 1));
    m0 = fmaxf(m0, __shfl_xor_sync(0xffffffffu, m0, 2));
    m1 = fmaxf(m1, __shfl_xor_sync(0xffffffffu, m1, 1));
    m1 = fmaxf(m1, __shfl_xor_sync(0xffffffffu, m1, 2));

    float* redM = (float*)(sm + OFF_RED);
    float* redS = redM + 128;
    const int r0 = mt * 16 + lr, r1 = r0 + 8;
    if (lc == 0) { redM[nh * 64 + r0] = m0; redM[nh * 64 + r1] = m1; }
    __syncthreads();
    float g0 = fmaxf(redM[r0], redM[64 + r0]);
    float g1 = fmaxf(redM[r1], redM[64 + r1]);

    float s0 = 0.f, s1 = 0.f;
#pragma unroll
    for (int nt = 0; nt < 8; nt++) {
        c[nt][0] = __expf(c[nt][0] - g0);
        c[nt][1] = __expf(c[nt][1] - g0);
        c[nt][2] = __expf(c[nt][2] - g1);
        c[nt][3] = __expf(c[nt][3] - g1);
        s0 += c[nt][0] + c[nt][1];
        s1 += c[nt][2] + c[nt][3];
    }
    s0 += __shfl_xor_sync(0xffffffffu, s0, 1);
    s0 += __shfl_xor_sync(0xffffffffu, s0, 2);
    s1 += __shfl_xor_sync(0xffffffffu, s1, 1);
    s1 += __shfl_xor_sync(0xffffffffu, s1, 2);
    if (lc == 0) { redS[nh * 64 + r0] = s0; redS[nh * 64 + r1] = s1; }
    __syncthreads();
    float inv0 = 1.f / (redS[r0] + redS[64 + r0]);
    float inv1 = 1.f / (redS[r1] + redS[64 + r1]);

    // ---- pack P (fp16) ----
    uint32_t* sP = sm + OFF_P;
#pragma unroll
    for (int nt = 0; nt < 8; nt++) {
        __half2 p01 = __floats2half2_rn(c[nt][0] * inv0, c[nt][1] * inv0);
        __half2 p23 = __floats2half2_rn(c[nt][2] * inv1, c[nt][3] * inv1);
        int idx = r0 * AP + nh * 32 + nt * 4 + lc;
        sP[idx] = *(uint32_t*)&p01;
        sP[idx + 8 * AP] = *(uint32_t*)&p23;
    }
    __syncthreads();

    // ---- phase 3: out = P @ V2 (B via ldmatrix.trans on row-major V2) ----
    float o[8][4];
#pragma unroll
    for (int nt = 0; nt < 8; nt++)
#pragma unroll
        for (int r = 0; r < 4; r++) o[nt][r] = 0.f;

#pragma unroll
    for (int ks = 0; ks < 8; ks++) {
        uint32_t a[4];
        ldsm_x4(a, smbase + (uint32_t)((OFF_P + (mt * 16) * AP + ks * 8) * 4) + a_loff * 4);
#pragma unroll
        for (int nt = 0; nt < 8; nt++) {
            uint32_t b[2];
            ldsm_x2_t(b, smbase + (uint32_t)((OFF_V + (ks * 16) * AP + nh * 32 + nt * 4) * 4)
                                + t_loff * 4);
            mma16816h(o[nt], a, b);
        }
    }

    // ---- epilogue: fp16 AO into g_Ah ----
    const int bb = bh >> 3, hh = bh & 7;
    const size_t row0 = (size_t)bb * TT + u * BSZ + mt * 16 + lr;
#pragma unroll
    for (int nt = 0; nt < 8; nt++) {
        int col = hh * 128 + nh * 64 + nt * 8 + lc * 2;
        *(__half2*)(g_Ah + row0 * DD + col)       = __floats2half2_rn(o[nt][0], o[nt][1]);
        *(__half2*)(g_Ah + (row0 + 8) * DD + col) = __floats2half2_rn(o[nt][2], o[nt][3]);
    }
}

// ============================================================================
extern "C" void kernel_launch(void* const* d_in, const int* in_sizes, int n_in,
                              void* d_out, int out_size) {
    const float* x      = (const float*)d_in[0];
    const float* w_qkv  = (const float*)d_in[1];
    const float* sort_w = (const float*)d_in[2];
    const float* w_out  = (const float*)d_in[3];
    const float* b_out  = (const float*)d_in[4];
    const float* noise  = (const float*)d_in[5];
    float* out = (float*)d_out;

    cudaFuncSetAttribute(attention_mma,
                         cudaFuncAttributeMaxDynamicSharedMemorySize, ATTN_SMEM_B);
    cudaFuncSetAttribute(gemm_h<true>,
                         cudaFuncAttributeMaxDynamicSharedMemorySize, GSMEM_BYTES);
    cudaFuncSetAttribute(gemm_h<false>,
                         cudaFuncAttributeMaxDynamicSharedMemorySize, GSMEM_BYTES);

    const int NF4_X  = 16384 * 1024 / 4;
    const int NF4_WQ = 3072 * 1024 / 4;
    const int NF4_WO = 1024 * 1024 / 4;

    cvt_kernel<<<NF4_X / 256, 256>>>(x, NF4_X, 0);
    cvt_kernel<<<NF4_WQ / 256, 256>>>(w_qkv, NF4_WQ, 2);
    gemm_h<true><<<dim3(24, 128), 256, GSMEM_BYTES>>>(nullptr, nullptr);
    bucket_sum<<<BHTOT * BUCKETS, 128>>>();
    sinkhorn_kernel<<<BHTOT, 256>>>(sort_w, noise);
    permute_kv2h<<<dim3(32, BHTOT, 2), 256>>>();
    attention_mma<<<dim3(BUCKETS, BHTOT), 256, ATTN_SMEM_B>>>();
    cvt_kernel<<<NF4_WO / 256, 256>>>(w_out, NF4_WO, 2);
    gemm_h<false><<<dim3(8, 128), 256, GSMEM_BYTES>>>(b_out, out);
}